// round 6
// baseline (speedup 1.0000x reference)
#include <cuda_runtime.h>
#include <cuda_bf16.h>
#include <cstdint>

// Decoder: 2-layer LSTM + Luong attention. T=B=S=64, H=E=1024, L=2.
// Warp-level mma.sync bf16 (3-way split), 64x32 tiles, 3-stage cp.async
// pipeline, load-balanced pipelined step launches.

#define TT 64
#define BB 64
#define SS 64
#define HH 1024
#define BH (BB * HH)

typedef unsigned long long ull;
typedef __nv_bfloat16 bf16;

__device__ __forceinline__ float sigm_(float x) { return 1.f / (1.f + expf(-x)); }
__device__ __forceinline__ void split2(float v, bf16& hi, bf16& lo) {
    hi = __float2bfloat16(v);
    lo = __float2bfloat16(v - __bfloat162float(hi));
}

// ------------------------------- scratch -------------------------------
__device__ __align__(256) bf16 g_Wih_h[8388608], g_Wih_l[8388608];
__device__ __align__(256) bf16 g_Whh_h[8388608], g_Whh_l[8388608];
__device__ __align__(256) bf16 g_Win_h[1048576], g_Win_l[1048576];
__device__ __align__(256) bf16 g_Wo_h[2097152],  g_Wo_l[2097152];
__device__ __align__(256) bf16 g_XEh[4194304],   g_XEl[4194304];
__device__ float g_X0[(size_t)4096 * 4096];        // [t*64+b][4096 gate cols]
__device__ float g_h0F[2][BH], g_h1F[4][BH], g_c0F[BH], g_c1F[BH];
__device__ __align__(256) bf16 g_h0H[2][BH], g_h0L[2][BH];
__device__ __align__(256) bf16 g_h1H[4][BH], g_h1L[4][BH];
__device__ __align__(256) bf16 g_wcH[2][BH], g_wcL[2][BH];
__device__ float g_qF[2][BH];
__device__ float g_attn[BB * SS];

// ----------------------------- ptx helpers -----------------------------
__device__ __forceinline__ uint32_t s2u(const void* p) {
    uint32_t a;
    asm("{ .reg .u64 t; cvta.to.shared.u64 t, %1; cvt.u32.u64 %0, t; }"
        : "=r"(a) : "l"(p));
    return a;
}
__device__ __forceinline__ void cpa16(uint32_t dst, const void* src) {
    asm volatile("cp.async.cg.shared.global [%0], [%1], 16;"
                 :: "r"(dst), "l"(src) : "memory");
}
__device__ __forceinline__ void ldsm4(uint32_t* r, uint32_t addr) {
    asm volatile("ldmatrix.sync.aligned.m8n8.x4.shared.b16 {%0,%1,%2,%3}, [%4];"
                 : "=r"(r[0]), "=r"(r[1]), "=r"(r[2]), "=r"(r[3]) : "r"(addr));
}
__device__ __forceinline__ void mma16816(float* d, const uint32_t* a, const uint32_t* b) {
    asm volatile(
        "mma.sync.aligned.m16n8k16.row.col.f32.bf16.bf16.f32 "
        "{%0,%1,%2,%3},{%4,%5,%6,%7},{%8,%9},{%0,%1,%2,%3};"
        : "+f"(d[0]), "+f"(d[1]), "+f"(d[2]), "+f"(d[3])
        : "r"(a[0]), "r"(a[1]), "r"(a[2]), "r"(a[3]), "r"(b[0]), "r"(b[1]));
}

// ---------------------------- GEMM segment -----------------------------
// C[64 m(batch), 32 n] = A @ W^T.  A rows [m][1024] bf16 hi/lo; W rows [n][wld].
// GATE: n cols = 4 gates x 8 hidden units. PAIR2: K=2048 (concat).
// EPI 0 = fused LSTM cell, 1 = plain store (opt bias/tanh).
struct Seg {
    const bf16 *A1h, *A1l, *A2h, *A2l;
    const bf16 *W1h, *W1l, *W2h, *W2l;
    int wld, K;
    const float *addC, *bias1, *bias2;
    float *cSt, *hF;
    bf16 *hH, *hL;
    float *outC; int ldC, doTanh;
};

// smem: 3 stages x (Ah 5120 | Al 5120 | Wh 2560 | Wl 2560) = 46080 bytes.
// Rows padded to 80B (k32 = 64B + 16B pad) -> conflict-free ldmatrix.
#define STG 15360
#define SMB (3 * STG)

template <bool GATE, bool PAIR2, int EPI>
__device__ void mgemm(const Seg& a, char* sm, int mblk, int nblk) {
    const int tx = threadIdx.x;
    const int wid = tx >> 5, lane = tx & 31;
    const int wm = (wid & 3) << 4;       // warp m offset 0..48
    const int wn = (wid >> 2) << 4;      // warp n offset 0 or 16
    const uint32_t smb = s2u(sm);

    // A staging: row sr (0..63), 16B unit su (0..3)
    const int sr = tx >> 2, su = tx & 3;
    const int am = mblk * 64 + sr;
    // W staging: u = tx&127 -> local row wrl (0..31), unit wu; tx>=128 -> lo part
    const int u = tx & 127;
    const int wrl = u >> 2, wu = u & 3;
    const int wr = GATE ? ((wrl >> 3) * HH + nblk * 8 + (wrl & 7))
                        : (nblk * 32 + wrl);
    const int wlo = tx >> 7;             // 0: Wh, 1: Wl

    float acc[2][4] = {};
    const int nc = a.K >> 5;

    const uint32_t aoff = (uint32_t)((wm + (lane & 15)) * 80 + ((lane >> 4) << 4));
    const uint32_t boff = (uint32_t)(10240 + (wn + ((lane >> 4) << 3) + (lane & 7)) * 80
                                     + (((lane >> 3) & 1) << 4));

#define STAGE(c)                                                               \
    {                                                                          \
        int kg = (c) << 5;                                                     \
        const bf16 *a1, *a2, *w1, *w2; int kl;                                 \
        if (PAIR2 && kg >= 1024) {                                             \
            a1 = a.A2h; a2 = a.A2l; w1 = a.W2h; w2 = a.W2l; kl = kg - 1024;    \
        } else {                                                               \
            a1 = a.A1h; a2 = a.A1l; w1 = a.W1h; w2 = a.W1l; kl = kg;           \
        }                                                                      \
        uint32_t db = smb + ((c) % 3) * STG;                                   \
        size_t ao = (size_t)am * 1024 + kl + su * 8;                           \
        cpa16(db + sr * 80 + (su << 4), a1 + ao);                              \
        cpa16(db + 5120 + sr * 80 + (su << 4), a2 + ao);                       \
        size_t wo = (size_t)wr * a.wld + kl + wu * 8;                          \
        cpa16(db + 10240 + wlo * 2560 + wrl * 80 + (wu << 4),                  \
              (wlo ? w2 : w1) + wo);                                           \
        asm volatile("cp.async.commit_group;" ::: "memory");                   \
    }

    STAGE(0)
    STAGE(1)
    for (int c = 0; c < nc; ++c) {
        if (c + 2 < nc) {
            STAGE(c + 2)
            asm volatile("cp.async.wait_group 2;" ::: "memory");
        } else if (c + 1 < nc) {
            asm volatile("cp.async.wait_group 1;" ::: "memory");
        } else {
            asm volatile("cp.async.wait_group 0;" ::: "memory");
        }
        __syncthreads();
        const uint32_t base = smb + (c % 3) * STG;
#pragma unroll
        for (int kk = 0; kk < 2; ++kk) {
            uint32_t ah[4], al[4], bh[4], bl[4];
            ldsm4(ah, base + aoff + kk * 32);
            ldsm4(al, base + 5120 + aoff + kk * 32);
            ldsm4(bh, base + boff + kk * 32);
            ldsm4(bl, base + boff + 2560 + kk * 32);
#pragma unroll
            for (int nt = 0; nt < 2; ++nt) {
                mma16816(acc[nt], ah, bh + 2 * nt);
                mma16816(acc[nt], ah, bl + 2 * nt);
                mma16816(acc[nt], al, bh + 2 * nt);
            }
        }
        __syncthreads();
    }
#undef STAGE

    // stage C to smem as St[col][row], pitch 66 (conflict-free)
    float* St = (float*)sm;
    const int rr = wm + (lane >> 2);
#pragma unroll
    for (int nt = 0; nt < 2; ++nt) {
        int cc = wn + nt * 8 + ((lane & 3) << 1);
        St[cc * 66 + rr]           = acc[nt][0];
        St[(cc + 1) * 66 + rr]     = acc[nt][1];
        St[cc * 66 + rr + 8]       = acc[nt][2];
        St[(cc + 1) * 66 + rr + 8] = acc[nt][3];
    }
    __syncthreads();

    if (EPI == 0) {      // fused LSTM cell: cols = gate*8 + jj
#pragma unroll
        for (int it = 0; it < 2; ++it) {
            int idx = tx + it * 256;
            int b = idx & 63, jj = idx >> 6;          // jj 0..7
            int jg = nblk * 8 + jj;
            float gi = St[jj * 66 + b];
            float gf = St[(8 + jj) * 66 + b];
            float gg = St[(16 + jj) * 66 + b];
            float go = St[(24 + jj) * 66 + b];
            if (a.addC) {
                const float* ac = a.addC + (size_t)b * 4096 + jg;
                gi += ac[0]; gf += ac[1024]; gg += ac[2048]; go += ac[3072];
            }
            if (a.bias1) {
                gi += a.bias1[jg] + a.bias2[jg];
                gf += a.bias1[1024 + jg] + a.bias2[1024 + jg];
                gg += a.bias1[2048 + jg] + a.bias2[2048 + jg];
                go += a.bias1[3072 + jg] + a.bias2[3072 + jg];
            }
            float cc2 = sigm_(gf) * a.cSt[b * HH + jg] + sigm_(gi) * tanhf(gg);
            a.cSt[b * HH + jg] = cc2;
            float h = sigm_(go) * tanhf(cc2);
            a.hF[b * HH + jg] = h;
            split2(h, a.hH[b * HH + jg], a.hL[b * HH + jg]);
        }
    } else {             // plain store (optional bias / tanh)
#pragma unroll
        for (int it = 0; it < 8; ++it) {
            int idx = tx + it * 256;
            int row = idx >> 5, col = idx & 31;
            float v = St[col * 66 + row];
            int cg = nblk * 32 + col;
            if (a.bias1) v += a.bias1[cg] + a.bias2[cg];
            if (a.doTanh) v = tanhf(v);
            a.outC[(size_t)(mblk * 64 + row) * a.ldC + cg] = v;
        }
    }
}

// ------------------------------ step kernel ----------------------------
struct StepP {
    int nL1, nOut, nL0, nQ, nAt;
    Seg l1, o, l0, q;
    const float *atQ, *atCtx;
    bf16 *atWcH, *atWcL;
    float* atP;
};

__global__ __launch_bounds__(256) void step_k(StepP p) {
    __shared__ __align__(16) char sm[SMB];
    const int bid = blockIdx.x;
    const int r0 = p.nL1, r1 = r0 + p.nOut, r2 = r1 + p.nL0, r3 = r2 + p.nQ;

    if (bid < r0) {
        mgemm<true, true, 0>(p.l1, sm, 0, bid);
    } else if (bid < r1) {
        mgemm<false, true, 1>(p.o, sm, 0, bid - r0);
    } else if (bid < r2) {
        mgemm<true, false, 0>(p.l0, sm, 0, bid - r1);
    } else if (bid < r3) {
        mgemm<false, false, 1>(p.q, sm, 0, bid - r2);
    } else {                              // ATTN: one block per batch b
        int b = bid - r3;
        float* qs = (float*)sm;           // 1024 floats
        float* sc = qs + 1024;            // 64 floats
        const int tx = threadIdx.x;
        *(float4*)&qs[tx * 4] = *(const float4*)&p.atQ[(size_t)b * HH + tx * 4];
        __syncthreads();
        const int wid = tx >> 5, lane = tx & 31;
        for (int s = wid; s < SS; s += 8) {
            const float* cp = p.atCtx + ((size_t)s * BB + b) * HH;
            float acc = 0.f;
#pragma unroll
            for (int i = 0; i < 8; ++i) {
                float4 c4 = *(const float4*)(cp + i * 128 + lane * 4);
                float4 q4 = *(const float4*)&qs[i * 128 + lane * 4];
                acc += c4.x * q4.x + c4.y * q4.y + c4.z * q4.z + c4.w * q4.w;
            }
#pragma unroll
            for (int o = 16; o; o >>= 1) acc += __shfl_down_sync(0xFFFFFFFFu, acc, o);
            if (lane == 0) sc[s] = acc;
        }
        __syncthreads();
        if (tx == 0) {
            float mx = sc[0];
            for (int s = 1; s < SS; ++s) mx = fmaxf(mx, sc[s]);
            float sum = 0.f;
            for (int s = 0; s < SS; ++s) { float e = expf(sc[s] - mx); sc[s] = e; sum += e; }
            float inv = 1.f / sum;
            for (int s = 0; s < SS; ++s) sc[s] *= inv;
        }
        __syncthreads();
        if (tx < SS) p.atP[b * SS + tx] = sc[tx];
        for (int k = tx; k < HH; k += 256) {
            float acc = 0.f;
#pragma unroll 8
            for (int s = 0; s < SS; ++s)
                acc += sc[s] * p.atCtx[((size_t)s * BB + b) * HH + k];
            split2(acc, p.atWcH[(size_t)b * HH + k], p.atWcL[(size_t)b * HH + k]);
        }
    }
}

// ---------------- X0 precompute: emb[input] @ w_ih0^T + biases ----------
__global__ __launch_bounds__(256) void x0_k(StepP p) {
    __shared__ __align__(16) char sm[SMB];
    mgemm<false, false, 1>(p.l0, sm, blockIdx.y, blockIdx.x);
}

// ----------------------------- init kernels ----------------------------
__global__ void split_w(const float* __restrict__ w_ih, const float* __restrict__ w_hh,
                        const float* __restrict__ w_in, const float* __restrict__ w_out) {
    const size_t N = 19922944;
    for (size_t i = (size_t)blockIdx.x * 256 + threadIdx.x; i < N;
         i += (size_t)gridDim.x * 256) {
        float v; bf16 *dh, *dl; size_t j;
        if (i < 8388608) {
            j = i; v = w_ih[j]; dh = g_Wih_h; dl = g_Wih_l;
        } else if (i < 16777216) {
            j = i - 8388608; v = w_hh[j]; dh = g_Whh_h; dl = g_Whh_l;
        } else if (i < 17825792) {
            j = i - 16777216; v = w_in[j]; dh = g_Win_h; dl = g_Win_l;
        } else {
            j = i - 17825792; v = w_out[j]; dh = g_Wo_h; dl = g_Wo_l;
        }
        split2(v, dh[j], dl[j]);
    }
}

__global__ void gather_xe(const int* __restrict__ inp, const float* __restrict__ emb) {
    size_t i = (size_t)blockIdx.x * 256 + threadIdx.x;
    if (i < 4194304) {
        size_t tb = i >> 10, k = i & 1023;
        float v = emb[(size_t)inp[tb] * 1024 + k];
        split2(v, g_XEh[i], g_XEl[i]);
    }
}

__global__ void init_sk(const float* __restrict__ h0, const float* __restrict__ c0) {
    int i = blockIdx.x * 256 + threadIdx.x;
    if (i < BH) {
        float a = h0[i], b = h0[BH + i];
        g_h0F[1][i] = a; split2(a, g_h0H[1][i], g_h0L[1][i]);   // h0(-1): slot 1
        g_h1F[3][i] = b; split2(b, g_h1H[3][i], g_h1L[3][i]);   // h1(-1): slot 3
        g_c0F[i] = c0[i];
        g_c1F[i] = c0[BH + i];
    }
}

__global__ void final_k(float* __restrict__ hf, float* __restrict__ cf,
                        float* __restrict__ at) {
    int i = blockIdx.x * 256 + threadIdx.x;
    if (i < BH) {
        hf[i] = g_h0F[1][i];            // h0(63): 63&1 = 1
        hf[BH + i] = g_h1F[3][i];       // h1(63): 63&3 = 3
        cf[i] = g_c0F[i];
        cf[BH + i] = g_c1F[i];
    }
    if (i < BB * SS) at[i] = g_attn[i];
}

// ------------------------------- launch --------------------------------
extern "C" void kernel_launch(void* const* d_in, const int* in_sizes, int n_in,
                              void* d_out, int out_size) {
    (void)in_sizes; (void)n_in; (void)out_size;
    const int*   inp   = (const int*)d_in[0];
    const float* h0    = (const float*)d_in[1];
    const float* c0    = (const float*)d_in[2];
    const float* ctx   = (const float*)d_in[3];
    const float* emb   = (const float*)d_in[4];
    const float* w_ih  = (const float*)d_in[5];
    const float* w_hh  = (const float*)d_in[6];
    const float* b_ih  = (const float*)d_in[7];
    const float* b_hh  = (const float*)d_in[8];
    const float* w_in  = (const float*)d_in[9];
    const float* w_out = (const float*)d_in[10];

    float* out  = (float*)d_out;
    float* outs = out;
    float* hf   = out + (size_t)TT * BH;
    float* cf   = hf + 2 * BH;
    float* at   = cf + 2 * BH;

    bf16 *WihH, *WihL, *WhhH, *WhhL, *WinH, *WinL, *WoH, *WoL, *XEh, *XEl;
    bf16 *h0H, *h0L, *h1H, *h1L, *wcH, *wcL;
    float *h0F, *h1F, *c0F, *c1F, *qF, *X0, *AT;
    cudaGetSymbolAddress((void**)&WihH, g_Wih_h); cudaGetSymbolAddress((void**)&WihL, g_Wih_l);
    cudaGetSymbolAddress((void**)&WhhH, g_Whh_h); cudaGetSymbolAddress((void**)&WhhL, g_Whh_l);
    cudaGetSymbolAddress((void**)&WinH, g_Win_h); cudaGetSymbolAddress((void**)&WinL, g_Win_l);
    cudaGetSymbolAddress((void**)&WoH,  g_Wo_h);  cudaGetSymbolAddress((void**)&WoL,  g_Wo_l);
    cudaGetSymbolAddress((void**)&XEh,  g_XEh);   cudaGetSymbolAddress((void**)&XEl,  g_XEl);
    cudaGetSymbolAddress((void**)&h0F, g_h0F); cudaGetSymbolAddress((void**)&h1F, g_h1F);
    cudaGetSymbolAddress((void**)&h0H, g_h0H); cudaGetSymbolAddress((void**)&h0L, g_h0L);
    cudaGetSymbolAddress((void**)&h1H, g_h1H); cudaGetSymbolAddress((void**)&h1L, g_h1L);
    cudaGetSymbolAddress((void**)&c0F, g_c0F); cudaGetSymbolAddress((void**)&c1F, g_c1F);
    cudaGetSymbolAddress((void**)&qF,  g_qF);
    cudaGetSymbolAddress((void**)&wcH, g_wcH); cudaGetSymbolAddress((void**)&wcL, g_wcL);
    cudaGetSymbolAddress((void**)&X0,  g_X0);
    cudaGetSymbolAddress((void**)&AT,  g_attn);

    split_w<<<16384, 256>>>(w_ih, w_hh, w_in, w_out);
    gather_xe<<<16384, 256>>>(inp, emb);
    init_sk<<<256, 256>>>(h0, c0);

    {   // X0 = XE @ w_ih0^T + b_ih0 + b_hh0, grid (128 nblk, 64 mblk)
        StepP p = {};
        Seg& s = p.l0;
        s.A1h = XEh; s.A1l = XEl;
        s.W1h = WihH; s.W1l = WihL; s.wld = 1024; s.K = 1024;
        s.bias1 = b_ih; s.bias2 = b_hh;
        s.outC = X0; s.ldC = 4096; s.doTanh = 0;
        x0_k<<<dim3(128, 64), 256>>>(p);
    }

    // Pipeline: launch k carries L1(k-1), OUT(k-4), L0(k), Q(k-2), ATTN(k-3).
    for (int k = 0; k <= 67; ++k) {
        StepP p = {};
        int tL1 = k - 1, tL0 = k, tQ = k - 2, tAt = k - 3, tOut = k - 4;
        if (tL1 >= 0 && tL1 < TT) {
            p.nL1 = 128;
            Seg& s = p.l1;
            s.A1h = h0H + (size_t)(tL1 & 1) * BH; s.A1l = h0L + (size_t)(tL1 & 1) * BH;
            s.A2h = h1H + (size_t)((tL1 - 1) & 3) * BH;
            s.A2l = h1L + (size_t)((tL1 - 1) & 3) * BH;
            s.W1h = WihH + 4194304; s.W1l = WihL + 4194304;
            s.W2h = WhhH + 4194304; s.W2l = WhhL + 4194304;
            s.wld = 1024; s.K = 2048;
            s.bias1 = b_ih + 4096; s.bias2 = b_hh + 4096;
            s.cSt = c1F;
            s.hF = h1F + (size_t)(tL1 & 3) * BH;
            s.hH = h1H + (size_t)(tL1 & 3) * BH;
            s.hL = h1L + (size_t)(tL1 & 3) * BH;
        }
        if (tOut >= 0 && tOut < TT) {
            p.nOut = 32;
            Seg& s = p.o;
            s.A1h = wcH + (size_t)(tOut & 1) * BH; s.A1l = wcL + (size_t)(tOut & 1) * BH;
            s.A2h = h1H + (size_t)(tOut & 3) * BH; s.A2l = h1L + (size_t)(tOut & 3) * BH;
            s.W1h = WoH; s.W1l = WoL;
            s.W2h = WoH + 1024; s.W2l = WoL + 1024;
            s.wld = 2048; s.K = 2048;
            s.outC = outs + (size_t)tOut * BH; s.ldC = HH; s.doTanh = 1;
        }
        if (tL0 >= 0 && tL0 < TT) {
            p.nL0 = 128;
            Seg& s = p.l0;
            s.A1h = h0H + (size_t)((tL0 + 1) & 1) * BH;
            s.A1l = h0L + (size_t)((tL0 + 1) & 1) * BH;
            s.W1h = WhhH; s.W1l = WhhL; s.wld = 1024; s.K = 1024;
            s.addC = X0 + (size_t)tL0 * 64 * 4096;
            s.cSt = c0F;
            s.hF = h0F + (size_t)(tL0 & 1) * BH;
            s.hH = h0H + (size_t)(tL0 & 1) * BH;
            s.hL = h0L + (size_t)(tL0 & 1) * BH;
        }
        if (tQ >= 0 && tQ < TT) {
            p.nQ = 32;
            Seg& s = p.q;
            s.A1h = h1H + (size_t)(tQ & 3) * BH; s.A1l = h1L + (size_t)(tQ & 3) * BH;
            s.W1h = WinH; s.W1l = WinL; s.wld = 1024; s.K = 1024;
            s.outC = qF + (size_t)(tQ & 1) * BH; s.ldC = HH; s.doTanh = 0;
        }
        if (tAt >= 0 && tAt < TT) {
            p.nAt = 64;
            p.atQ = qF + (size_t)(tAt & 1) * BH;
            p.atCtx = ctx;
            p.atWcH = wcH + (size_t)(tAt & 1) * BH;
            p.atWcL = wcL + (size_t)(tAt & 1) * BH;
            p.atP = AT;
        }
        int grid = p.nL1 + p.nOut + p.nL0 + p.nQ + p.nAt;
        if (grid > 0) step_k<<<grid, 256>>>(p);
    }

    final_k<<<512, 256>>>(hf, cf, at);
}

// round 7
// speedup vs baseline: 1.1441x; 1.1441x over previous
#include <cuda_runtime.h>
#include <cuda_bf16.h>
#include <cstdint>

// Decoder: 2-layer LSTM + Luong attention. T=B=S=64, H=E=1024, L=2.
// mma.sync bf16 (3-way split), 64x64 tiles, 512-thread blocks with
// warpgroup K-split, pipelined one-launch-per-step schedule.

#define TT 64
#define BB 64
#define SS 64
#define HH 1024
#define BH (BB * HH)

typedef unsigned long long ull;
typedef __nv_bfloat16 bf16;

__device__ __forceinline__ float sigm_(float x) { return 1.f / (1.f + expf(-x)); }
__device__ __forceinline__ void split2(float v, bf16& hi, bf16& lo) {
    hi = __float2bfloat16(v);
    lo = __float2bfloat16(v - __bfloat162float(hi));
}

// ------------------------------- scratch -------------------------------
__device__ __align__(256) bf16 g_Wih_h[8388608], g_Wih_l[8388608];
__device__ __align__(256) bf16 g_Whh_h[8388608], g_Whh_l[8388608];
__device__ __align__(256) bf16 g_Win_h[1048576], g_Win_l[1048576];
__device__ __align__(256) bf16 g_Wo_h[2097152],  g_Wo_l[2097152];
__device__ __align__(256) bf16 g_XEh[4194304],   g_XEl[4194304];
__device__ float g_X0[(size_t)4096 * 4096];        // [t*64+b][4096 gate cols]
__device__ float g_h0F[2][BH], g_h1F[4][BH], g_c0F[BH], g_c1F[BH];
__device__ __align__(256) bf16 g_h0H[2][BH], g_h0L[2][BH];
__device__ __align__(256) bf16 g_h1H[4][BH], g_h1L[4][BH];
__device__ __align__(256) bf16 g_wcH[2][BH], g_wcL[2][BH];
__device__ float g_qF[2][BH];
__device__ float g_attn[BB * SS];

// ----------------------------- ptx helpers -----------------------------
__device__ __forceinline__ uint32_t s2u(const void* p) {
    uint32_t a;
    asm("{ .reg .u64 t; cvta.to.shared.u64 t, %1; cvt.u32.u64 %0, t; }"
        : "=r"(a) : "l"(p));
    return a;
}
__device__ __forceinline__ void cpa16(uint32_t dst, const void* src) {
    asm volatile("cp.async.cg.shared.global [%0], [%1], 16;"
                 :: "r"(dst), "l"(src) : "memory");
}
__device__ __forceinline__ void ldsm4(uint32_t* r, uint32_t addr) {
    asm volatile("ldmatrix.sync.aligned.m8n8.x4.shared.b16 {%0,%1,%2,%3}, [%4];"
                 : "=r"(r[0]), "=r"(r[1]), "=r"(r[2]), "=r"(r[3]) : "r"(addr));
}
__device__ __forceinline__ void mma16816(float* d, const uint32_t* a, const uint32_t* b) {
    asm volatile(
        "mma.sync.aligned.m16n8k16.row.col.f32.bf16.bf16.f32 "
        "{%0,%1,%2,%3},{%4,%5,%6,%7},{%8,%9},{%0,%1,%2,%3};"
        : "+f"(d[0]), "+f"(d[1]), "+f"(d[2]), "+f"(d[3])
        : "r"(a[0]), "r"(a[1]), "r"(a[2]), "r"(a[3]), "r"(b[0]), "r"(b[1]));
}

// ---------------------------- GEMM segment -----------------------------
// C[64 m(batch), 64 n] = A @ W^T. 512 threads: wg0/wg1 each compute half
// of K into separate partial accumulators; combined in epilogue.
// GATE: n cols = 4 gates x 16 hidden units. PAIR2: K=2048 (wg = pair half).
struct Seg {
    const bf16 *A1h, *A1l, *A2h, *A2l;
    const bf16 *W1h, *W1l, *W2h, *W2l;
    int wld, K;
    const float *addC, *bias1, *bias2;
    float *cSt, *hF;
    bf16 *hH, *hL;
    float *outC; int ldC, doTanh;
};

// per-wg: 2 stages x (Ah 5120 | Al 5120 | Wh 5120 | Wl 5120) = 40960 B
// block total 81920 B dynamic smem. Rows padded to 80B -> no bank conflicts.
#define WGB 40960
#define SMB 81920

template <bool GATE, bool PAIR2, int EPI>
__device__ void mgemm(const Seg& a, char* sm, int mblk, int nblk) {
    const int tx = threadIdx.x;
    const int wg = tx >> 8;              // warpgroup 0/1
    const int wtx = tx & 255;
    const int wid = wtx >> 5, lane = tx & 31;
    const int wm = (wid & 3) << 4;       // warp m offset 0..48
    const int wn = (wid >> 2) << 5;      // warp n offset 0 or 32
    const uint32_t smb = s2u(sm) + wg * WGB;

    const int sr = wtx >> 2, su = wtx & 3;
    const int am = mblk * 64 + sr;
    const int wr = GATE ? ((sr >> 4) * HH + nblk * 16 + (sr & 15))
                        : (nblk * 64 + sr);

    // per-wg operands and K range
    const bf16 *a1, *a2, *w1, *w2;
    int kbase, Kwg;
    if (PAIR2) {
        a1 = wg ? a.A2h : a.A1h; a2 = wg ? a.A2l : a.A1l;
        w1 = wg ? a.W2h : a.W1h; w2 = wg ? a.W2l : a.W1l;
        kbase = 0; Kwg = 1024;
    } else {
        a1 = a.A1h; a2 = a.A1l; w1 = a.W1h; w2 = a.W1l;
        kbase = wg * (a.K >> 1); Kwg = a.K >> 1;
    }
    const size_t arow = (size_t)am * 1024;
    const size_t wrow = (size_t)wr * a.wld;

    float acc[4][4] = {};
    const int nc = Kwg >> 5;

    const uint32_t aoff = (uint32_t)((wm + (lane & 15)) * 80 + ((lane >> 4) << 4));
    const uint32_t boff = (uint32_t)((wn + ((lane >> 4) << 3) + (lane & 7)) * 80
                                     + (((lane >> 3) & 1) << 4));

#define STAGE(c)                                                               \
    {                                                                          \
        int kl = kbase + ((c) << 5);                                           \
        uint32_t db = smb + ((c) & 1) * 20480 + sr * 80 + (su << 4);           \
        size_t ao = arow + kl + su * 8;                                        \
        size_t wo = wrow + kl + su * 8;                                        \
        cpa16(db,         a1 + ao);                                            \
        cpa16(db + 5120,  a2 + ao);                                            \
        cpa16(db + 10240, w1 + wo);                                            \
        cpa16(db + 15360, w2 + wo);                                            \
        asm volatile("cp.async.commit_group;" ::: "memory");                   \
    }

    STAGE(0)
    for (int c = 0; c < nc; ++c) {
        if (c + 1 < nc) {
            STAGE(c + 1)
            asm volatile("cp.async.wait_group 1;" ::: "memory");
        } else {
            asm volatile("cp.async.wait_group 0;" ::: "memory");
        }
        __syncthreads();
        const uint32_t base = smb + (c & 1) * 20480;
#pragma unroll
        for (int kk = 0; kk < 2; ++kk) {
            uint32_t ah[4], al[4], bh[8], bl[8];
            ldsm4(ah, base + aoff + kk * 32);
            ldsm4(al, base + 5120 + aoff + kk * 32);
            ldsm4(bh,     base + 10240 + boff + kk * 32);
            ldsm4(bh + 4, base + 10240 + boff + 16 * 80 + kk * 32);
            ldsm4(bl,     base + 15360 + boff + kk * 32);
            ldsm4(bl + 4, base + 15360 + boff + 16 * 80 + kk * 32);
#pragma unroll
            for (int nt = 0; nt < 4; ++nt) {
                mma16816(acc[nt], ah, bh + 2 * nt);
                mma16816(acc[nt], ah, bl + 2 * nt);
                mma16816(acc[nt], al, bh + 2 * nt);
            }
        }
        __syncthreads();
    }
#undef STAGE

    // stage partial C to smem: wg0 -> St[0..4223], wg1 -> St[4224..8447]
    float* St = (float*)sm;
    float* Sw = St + wg * 4224;          // 64*66
    const int rr = wm + (lane >> 2);
#pragma unroll
    for (int nt = 0; nt < 4; ++nt) {
        int cc = wn + nt * 8 + ((lane & 3) << 1);
        Sw[cc * 66 + rr]           = acc[nt][0];
        Sw[(cc + 1) * 66 + rr]     = acc[nt][1];
        Sw[cc * 66 + rr + 8]       = acc[nt][2];
        Sw[(cc + 1) * 66 + rr + 8] = acc[nt][3];
    }
    __syncthreads();

    if (EPI == 0) {      // fused LSTM cell: cols = gate*16 + jj
#pragma unroll
        for (int it = 0; it < 2; ++it) {
            int idx = tx + it * 512;
            int b = idx & 63, jj = idx >> 6;          // jj 0..15
            int jg = nblk * 16 + jj;
            float gi = St[jj * 66 + b]        + St[4224 + jj * 66 + b];
            float gf = St[(16 + jj) * 66 + b] + St[4224 + (16 + jj) * 66 + b];
            float gg = St[(32 + jj) * 66 + b] + St[4224 + (32 + jj) * 66 + b];
            float go = St[(48 + jj) * 66 + b] + St[4224 + (48 + jj) * 66 + b];
            if (a.addC) {
                const float* ac = a.addC + (size_t)b * 4096 + jg;
                gi += ac[0]; gf += ac[1024]; gg += ac[2048]; go += ac[3072];
            }
            if (a.bias1) {
                gi += a.bias1[jg] + a.bias2[jg];
                gf += a.bias1[1024 + jg] + a.bias2[1024 + jg];
                gg += a.bias1[2048 + jg] + a.bias2[2048 + jg];
                go += a.bias1[3072 + jg] + a.bias2[3072 + jg];
            }
            float cc2 = sigm_(gf) * a.cSt[b * HH + jg] + sigm_(gi) * tanhf(gg);
            a.cSt[b * HH + jg] = cc2;
            float h = sigm_(go) * tanhf(cc2);
            a.hF[b * HH + jg] = h;
            split2(h, a.hH[b * HH + jg], a.hL[b * HH + jg]);
        }
    } else {             // plain store (optional bias / tanh)
#pragma unroll
        for (int it = 0; it < 8; ++it) {
            int idx = tx + it * 512;
            int row = idx >> 6, col = idx & 63;
            float v = St[col * 66 + row] + St[4224 + col * 66 + row];
            int cg = nblk * 64 + col;
            if (a.bias1) v += a.bias1[cg] + a.bias2[cg];
            if (a.doTanh) v = tanhf(v);
            a.outC[(size_t)(mblk * 64 + row) * a.ldC + cg] = v;
        }
    }
}

// ------------------------------ step kernel ----------------------------
struct StepP {
    int nL1, nOut, nL0, nQ, nAt;
    Seg l1, o, l0, q;
    const float *atQ, *atCtx;
    bf16 *atWcH, *atWcL;
    float* atP;
};

__global__ __launch_bounds__(512, 2) void step_k(StepP p) {
    extern __shared__ __align__(16) char sm[];
    const int bid = blockIdx.x;
    const int r0 = p.nL1, r1 = r0 + p.nOut, r2 = r1 + p.nL0, r3 = r2 + p.nQ;

    if (bid < r0) {
        mgemm<true, true, 0>(p.l1, sm, 0, bid);
    } else if (bid < r1) {
        mgemm<false, true, 1>(p.o, sm, 0, bid - r0);
    } else if (bid < r2) {
        mgemm<true, false, 0>(p.l0, sm, 0, bid - r1);
    } else if (bid < r3) {
        mgemm<false, false, 1>(p.q, sm, 0, bid - r2);
    } else {                              // ATTN: one block per batch b
        int b = bid - r3;
        float* qs = (float*)sm;           // 1024 floats
        float* sc = qs + 1024;            // 64 floats
        const int tx = threadIdx.x;
        *(float2*)&qs[tx * 2] = *(const float2*)&p.atQ[(size_t)b * HH + tx * 2];
        __syncthreads();
        const int wid = tx >> 5, lane = tx & 31;
        for (int s = wid; s < SS; s += 16) {
            const float* cp = p.atCtx + ((size_t)s * BB + b) * HH;
            float acc = 0.f;
#pragma unroll
            for (int i = 0; i < 8; ++i) {
                float4 c4 = *(const float4*)(cp + i * 128 + lane * 4);
                float4 q4 = *(const float4*)&qs[i * 128 + lane * 4];
                acc += c4.x * q4.x + c4.y * q4.y + c4.z * q4.z + c4.w * q4.w;
            }
#pragma unroll
            for (int o = 16; o; o >>= 1) acc += __shfl_down_sync(0xFFFFFFFFu, acc, o);
            if (lane == 0) sc[s] = acc;
        }
        __syncthreads();
        if (tx == 0) {
            float mx = sc[0];
            for (int s = 1; s < SS; ++s) mx = fmaxf(mx, sc[s]);
            float sum = 0.f;
            for (int s = 0; s < SS; ++s) { float e = expf(sc[s] - mx); sc[s] = e; sum += e; }
            float inv = 1.f / sum;
            for (int s = 0; s < SS; ++s) sc[s] *= inv;
        }
        __syncthreads();
        if (tx < SS) p.atP[b * SS + tx] = sc[tx];
        for (int k = tx; k < HH; k += 512) {
            float acc = 0.f;
#pragma unroll 8
            for (int s = 0; s < SS; ++s)
                acc += sc[s] * p.atCtx[((size_t)s * BB + b) * HH + k];
            split2(acc, p.atWcH[(size_t)b * HH + k], p.atWcL[(size_t)b * HH + k]);
        }
    }
}

// ---------------- X0 precompute: emb[input] @ w_ih0^T + biases ----------
__global__ __launch_bounds__(512, 2) void x0_k(StepP p) {
    extern __shared__ __align__(16) char sm[];
    mgemm<false, false, 1>(p.l0, sm, blockIdx.y, blockIdx.x);
}

// ----------------------------- init kernels ----------------------------
__global__ void split_w(const float* __restrict__ w_ih, const float* __restrict__ w_hh,
                        const float* __restrict__ w_in, const float* __restrict__ w_out) {
    const size_t N = 19922944;
    for (size_t i = (size_t)blockIdx.x * 256 + threadIdx.x; i < N;
         i += (size_t)gridDim.x * 256) {
        float v; bf16 *dh, *dl; size_t j;
        if (i < 8388608) {
            j = i; v = w_ih[j]; dh = g_Wih_h; dl = g_Wih_l;
        } else if (i < 16777216) {
            j = i - 8388608; v = w_hh[j]; dh = g_Whh_h; dl = g_Whh_l;
        } else if (i < 17825792) {
            j = i - 16777216; v = w_in[j]; dh = g_Win_h; dl = g_Win_l;
        } else {
            j = i - 17825792; v = w_out[j]; dh = g_Wo_h; dl = g_Wo_l;
        }
        split2(v, dh[j], dl[j]);
    }
}

__global__ void gather_xe(const int* __restrict__ inp, const float* __restrict__ emb) {
    size_t i = (size_t)blockIdx.x * 256 + threadIdx.x;
    if (i < 4194304) {
        size_t tb = i >> 10, k = i & 1023;
        float v = emb[(size_t)inp[tb] * 1024 + k];
        split2(v, g_XEh[i], g_XEl[i]);
    }
}

__global__ void init_sk(const float* __restrict__ h0, const float* __restrict__ c0) {
    int i = blockIdx.x * 256 + threadIdx.x;
    if (i < BH) {
        float a = h0[i], b = h0[BH + i];
        g_h0F[1][i] = a; split2(a, g_h0H[1][i], g_h0L[1][i]);   // h0(-1): slot 1
        g_h1F[3][i] = b; split2(b, g_h1H[3][i], g_h1L[3][i]);   // h1(-1): slot 3
        g_c0F[i] = c0[i];
        g_c1F[i] = c0[BH + i];
    }
}

__global__ void final_k(float* __restrict__ hf, float* __restrict__ cf,
                        float* __restrict__ at) {
    int i = blockIdx.x * 256 + threadIdx.x;
    if (i < BH) {
        hf[i] = g_h0F[1][i];            // h0(63): 63&1 = 1
        hf[BH + i] = g_h1F[3][i];       // h1(63): 63&3 = 3
        cf[i] = g_c0F[i];
        cf[BH + i] = g_c1F[i];
    }
    if (i < BB * SS) at[i] = g_attn[i];
}

// ------------------------------- launch --------------------------------
extern "C" void kernel_launch(void* const* d_in, const int* in_sizes, int n_in,
                              void* d_out, int out_size) {
    (void)in_sizes; (void)n_in; (void)out_size;
    const int*   inp   = (const int*)d_in[0];
    const float* h0    = (const float*)d_in[1];
    const float* c0    = (const float*)d_in[2];
    const float* ctx   = (const float*)d_in[3];
    const float* emb   = (const float*)d_in[4];
    const float* w_ih  = (const float*)d_in[5];
    const float* w_hh  = (const float*)d_in[6];
    const float* b_ih  = (const float*)d_in[7];
    const float* b_hh  = (const float*)d_in[8];
    const float* w_in  = (const float*)d_in[9];
    const float* w_out = (const float*)d_in[10];

    float* out  = (float*)d_out;
    float* outs = out;
    float* hf   = out + (size_t)TT * BH;
    float* cf   = hf + 2 * BH;
    float* at   = cf + 2 * BH;

    cudaFuncSetAttribute(step_k, cudaFuncAttributeMaxDynamicSharedMemorySize, SMB);
    cudaFuncSetAttribute(x0_k,   cudaFuncAttributeMaxDynamicSharedMemorySize, SMB);

    bf16 *WihH, *WihL, *WhhH, *WhhL, *WinH, *WinL, *WoH, *WoL, *XEh, *XEl;
    bf16 *h0H, *h0L, *h1H, *h1L, *wcH, *wcL;
    float *h0F, *h1F, *c0F, *c1F, *qF, *X0, *AT;
    cudaGetSymbolAddress((void**)&WihH, g_Wih_h); cudaGetSymbolAddress((void**)&WihL, g_Wih_l);
    cudaGetSymbolAddress((void**)&WhhH, g_Whh_h); cudaGetSymbolAddress((void**)&WhhL, g_Whh_l);
    cudaGetSymbolAddress((void**)&WinH, g_Win_h); cudaGetSymbolAddress((void**)&WinL, g_Win_l);
    cudaGetSymbolAddress((void**)&WoH,  g_Wo_h);  cudaGetSymbolAddress((void**)&WoL,  g_Wo_l);
    cudaGetSymbolAddress((void**)&XEh,  g_XEh);   cudaGetSymbolAddress((void**)&XEl,  g_XEl);
    cudaGetSymbolAddress((void**)&h0F, g_h0F); cudaGetSymbolAddress((void**)&h1F, g_h1F);
    cudaGetSymbolAddress((void**)&h0H, g_h0H); cudaGetSymbolAddress((void**)&h0L, g_h0L);
    cudaGetSymbolAddress((void**)&h1H, g_h1H); cudaGetSymbolAddress((void**)&h1L, g_h1L);
    cudaGetSymbolAddress((void**)&c0F, g_c0F); cudaGetSymbolAddress((void**)&c1F, g_c1F);
    cudaGetSymbolAddress((void**)&qF,  g_qF);
    cudaGetSymbolAddress((void**)&wcH, g_wcH); cudaGetSymbolAddress((void**)&wcL, g_wcL);
    cudaGetSymbolAddress((void**)&X0,  g_X0);
    cudaGetSymbolAddress((void**)&AT,  g_attn);

    split_w<<<16384, 256>>>(w_ih, w_hh, w_in, w_out);
    gather_xe<<<16384, 256>>>(inp, emb);
    init_sk<<<256, 256>>>(h0, c0);

    {   // X0 = XE @ w_ih0^T + b_ih0 + b_hh0, grid (64 nblk, 64 mblk)
        StepP p = {};
        Seg& s = p.l0;
        s.A1h = XEh; s.A1l = XEl;
        s.W1h = WihH; s.W1l = WihL; s.wld = 1024; s.K = 1024;
        s.bias1 = b_ih; s.bias2 = b_hh;
        s.outC = X0; s.ldC = 4096; s.doTanh = 0;
        x0_k<<<dim3(64, 64), 512, SMB>>>(p);
    }

    // Pipeline: launch k carries L1(k-1), OUT(k-4), L0(k), Q(k-2), ATTN(k-3).
    for (int k = 0; k <= 67; ++k) {
        StepP p = {};
        int tL1 = k - 1, tL0 = k, tQ = k - 2, tAt = k - 3, tOut = k - 4;
        if (tL1 >= 0 && tL1 < TT) {
            p.nL1 = 64;
            Seg& s = p.l1;
            s.A1h = h0H + (size_t)(tL1 & 1) * BH; s.A1l = h0L + (size_t)(tL1 & 1) * BH;
            s.A2h = h1H + (size_t)((tL1 - 1) & 3) * BH;
            s.A2l = h1L + (size_t)((tL1 - 1) & 3) * BH;
            s.W1h = WihH + 4194304; s.W1l = WihL + 4194304;
            s.W2h = WhhH + 4194304; s.W2l = WhhL + 4194304;
            s.wld = 1024; s.K = 2048;
            s.bias1 = b_ih + 4096; s.bias2 = b_hh + 4096;
            s.cSt = c1F;
            s.hF = h1F + (size_t)(tL1 & 3) * BH;
            s.hH = h1H + (size_t)(tL1 & 3) * BH;
            s.hL = h1L + (size_t)(tL1 & 3) * BH;
        }
        if (tOut >= 0 && tOut < TT) {
            p.nOut = 16;
            Seg& s = p.o;
            s.A1h = wcH + (size_t)(tOut & 1) * BH; s.A1l = wcL + (size_t)(tOut & 1) * BH;
            s.A2h = h1H + (size_t)(tOut & 3) * BH; s.A2l = h1L + (size_t)(tOut & 3) * BH;
            s.W1h = WoH; s.W1l = WoL;
            s.W2h = WoH + 1024; s.W2l = WoL + 1024;
            s.wld = 2048; s.K = 2048;
            s.outC = outs + (size_t)tOut * BH; s.ldC = HH; s.doTanh = 1;
        }
        if (tL0 >= 0 && tL0 < TT) {
            p.nL0 = 64;
            Seg& s = p.l0;
            s.A1h = h0H + (size_t)((tL0 + 1) & 1) * BH;
            s.A1l = h0L + (size_t)((tL0 + 1) & 1) * BH;
            s.W1h = WhhH; s.W1l = WhhL; s.wld = 1024; s.K = 1024;
            s.addC = X0 + (size_t)tL0 * 64 * 4096;
            s.cSt = c0F;
            s.hF = h0F + (size_t)(tL0 & 1) * BH;
            s.hH = h0H + (size_t)(tL0 & 1) * BH;
            s.hL = h0L + (size_t)(tL0 & 1) * BH;
        }
        if (tQ >= 0 && tQ < TT) {
            p.nQ = 16;
            Seg& s = p.q;
            s.A1h = h1H + (size_t)(tQ & 3) * BH; s.A1l = h1L + (size_t)(tQ & 3) * BH;
            s.W1h = WinH; s.W1l = WinL; s.wld = 1024; s.K = 1024;
            s.outC = qF + (size_t)(tQ & 1) * BH; s.ldC = HH; s.doTanh = 0;
        }
        if (tAt >= 0 && tAt < TT) {
            p.nAt = 64;
            p.atQ = qF + (size_t)(tAt & 1) * BH;
            p.atCtx = ctx;
            p.atWcH = wcH + (size_t)(tAt & 1) * BH;
            p.atWcL = wcL + (size_t)(tAt & 1) * BH;
            p.atP = AT;
        }
        int grid = p.nL1 + p.nOut + p.nL0 + p.nQ + p.nAt;
        if (grid > 0) step_k<<<grid, 512, SMB>>>(p);
    }

    final_k<<<512, 256>>>(hf, cf, at);
}

// round 8
// speedup vs baseline: 1.3605x; 1.1891x over previous
#include <cuda_runtime.h>
#include <cuda_bf16.h>
#include <cstdint>

// Decoder: 2-layer LSTM + Luong attention. T=B=S=64, H=E=1024, L=2.
// mma.sync bf16 (3-way split), 64x64 tiles, 512-thread blocks with warpgroup
// K-split, 5-stage cp.async pipeline, per-wg named barriers.

#define TT 64
#define BB 64
#define SS 64
#define HH 1024
#define BH (BB * HH)

typedef unsigned long long ull;
typedef __nv_bfloat16 bf16;

__device__ __forceinline__ float sigm_(float x) { return 1.f / (1.f + expf(-x)); }
__device__ __forceinline__ void split2(float v, bf16& hi, bf16& lo) {
    hi = __float2bfloat16(v);
    lo = __float2bfloat16(v - __bfloat162float(hi));
}

// ------------------------------- scratch -------------------------------
__device__ __align__(256) bf16 g_Wih_h[8388608], g_Wih_l[8388608];
__device__ __align__(256) bf16 g_Whh_h[8388608], g_Whh_l[8388608];
__device__ __align__(256) bf16 g_Win_h[1048576], g_Win_l[1048576];
__device__ __align__(256) bf16 g_Wo_h[2097152],  g_Wo_l[2097152];
__device__ __align__(256) bf16 g_XEh[4194304],   g_XEl[4194304];
__device__ float g_X0[(size_t)4096 * 4096];        // [t*64+b][4096 gate cols]
__device__ float g_h0F[2][BH], g_h1F[4][BH], g_c0F[BH], g_c1F[BH];
__device__ __align__(256) bf16 g_h0H[2][BH], g_h0L[2][BH];
__device__ __align__(256) bf16 g_h1H[4][BH], g_h1L[4][BH];
__device__ __align__(256) bf16 g_wcH[2][BH], g_wcL[2][BH];
__device__ float g_qF[2][BH];
__device__ float g_attn[BB * SS];

// ----------------------------- ptx helpers -----------------------------
__device__ __forceinline__ uint32_t s2u(const void* p) {
    uint32_t a;
    asm("{ .reg .u64 t; cvta.to.shared.u64 t, %1; cvt.u32.u64 %0, t; }"
        : "=r"(a) : "l"(p));
    return a;
}
__device__ __forceinline__ void cpa16(uint32_t dst, const void* src) {
    asm volatile("cp.async.cg.shared.global [%0], [%1], 16;"
                 :: "r"(dst), "l"(src) : "memory");
}
__device__ __forceinline__ void ldsm4(uint32_t* r, uint32_t addr) {
    asm volatile("ldmatrix.sync.aligned.m8n8.x4.shared.b16 {%0,%1,%2,%3}, [%4];"
                 : "=r"(r[0]), "=r"(r[1]), "=r"(r[2]), "=r"(r[3]) : "r"(addr));
}
__device__ __forceinline__ void mma16816(float* d, const uint32_t* a, const uint32_t* b) {
    asm volatile(
        "mma.sync.aligned.m16n8k16.row.col.f32.bf16.bf16.f32 "
        "{%0,%1,%2,%3},{%4,%5,%6,%7},{%8,%9},{%0,%1,%2,%3};"
        : "+f"(d[0]), "+f"(d[1]), "+f"(d[2]), "+f"(d[3])
        : "r"(a[0]), "r"(a[1]), "r"(a[2]), "r"(a[3]), "r"(b[0]), "r"(b[1]));
}
__device__ __forceinline__ void barw(int wg) {
    asm volatile("bar.sync %0, 256;" :: "r"(wg + 1) : "memory");
}

// ---------------------------- GEMM segment -----------------------------
// C[64 m(batch), 64 n] = A @ W^T. 512 threads: wg0/wg1 each compute half
// of K into separate partial accumulators; combined in epilogue.
// GATE: n cols = 4 gates x 16 hidden units. PAIR2: K=2048 (wg = pair half).
struct Seg {
    const bf16 *A1h, *A1l, *A2h, *A2l;
    const bf16 *W1h, *W1l, *W2h, *W2l;
    int wld, K;
    const float *addC, *bias1, *bias2;
    float *cSt, *hF;
    bf16 *hH, *hL;
    float *outC; int ldC, doTanh;
};

// per-wg: 5 stages x (Ah 5120 | Al 5120 | Wh 5120 | Wl 5120) = 102400 B
// block total 204800 B dynamic smem. Rows padded to 80B -> no bank conflicts.
#define WGB 102400
#define SMB 204800

template <bool GATE, bool PAIR2, int EPI>
__device__ void mgemm(const Seg& a, char* sm, int mblk, int nblk) {
    const int tx = threadIdx.x;
    const int wg = tx >> 8;              // warpgroup 0/1
    const int wtx = tx & 255;
    const int wid = wtx >> 5, lane = tx & 31;
    const int wm = (wid & 3) << 4;       // warp m offset 0..48
    const int wn = (wid >> 2) << 5;      // warp n offset 0 or 32
    const uint32_t smb = s2u(sm) + wg * WGB;

    const int sr = wtx >> 2, su = wtx & 3;
    const int am = mblk * 64 + sr;
    const int wr = GATE ? ((sr >> 4) * HH + nblk * 16 + (sr & 15))
                        : (nblk * 64 + sr);

    // per-wg operands and K range
    const bf16 *a1, *a2, *w1, *w2;
    int kbase, Kwg;
    if (PAIR2) {
        a1 = wg ? a.A2h : a.A1h; a2 = wg ? a.A2l : a.A1l;
        w1 = wg ? a.W2h : a.W1h; w2 = wg ? a.W2l : a.W1l;
        kbase = 0; Kwg = 1024;
    } else {
        a1 = a.A1h; a2 = a.A1l; w1 = a.W1h; w2 = a.W1l;
        kbase = wg * (a.K >> 1); Kwg = a.K >> 1;
    }
    const size_t arow = (size_t)am * 1024;
    const size_t wrow = (size_t)wr * a.wld;

    float acc[4][4] = {};
    const int nc = Kwg >> 5;

    const uint32_t aoff = (uint32_t)((wm + (lane & 15)) * 80 + ((lane >> 4) << 4));
    const uint32_t boff = (uint32_t)((wn + ((lane >> 4) << 3) + (lane & 7)) * 80
                                     + (((lane >> 3) & 1) << 4));

#define STAGE(c)                                                               \
    {                                                                          \
        int kl = kbase + ((c) << 5);                                           \
        uint32_t db = smb + ((c) % 5) * 20480 + sr * 80 + (su << 4);           \
        size_t ao = arow + kl + su * 8;                                        \
        size_t wo = wrow + kl + su * 8;                                        \
        cpa16(db,         a1 + ao);                                            \
        cpa16(db + 5120,  a2 + ao);                                            \
        cpa16(db + 10240, w1 + wo);                                            \
        cpa16(db + 15360, w2 + wo);                                            \
        asm volatile("cp.async.commit_group;" ::: "memory");                   \
    }

    STAGE(0) STAGE(1) STAGE(2) STAGE(3)
    for (int c = 0; c < nc; ++c) {
        // wait for chunk c, barrier (covers buffer-reuse + visibility),
        // then prefetch c+4 into the buffer compute(c-1) just released.
        if (c + 4 < nc) {
            asm volatile("cp.async.wait_group 3;" ::: "memory");
            barw(wg);
            STAGE(c + 4)
        } else {
            asm volatile("cp.async.wait_group 0;" ::: "memory");
            barw(wg);
        }
        const uint32_t base = smb + (c % 5) * 20480;
#pragma unroll
        for (int kk = 0; kk < 2; ++kk) {
            uint32_t ah[4], al[4], bh[8], bl[8];
            ldsm4(ah, base + aoff + kk * 32);
            ldsm4(al, base + 5120 + aoff + kk * 32);
            ldsm4(bh,     base + 10240 + boff + kk * 32);
            ldsm4(bh + 4, base + 10240 + boff + 16 * 80 + kk * 32);
            ldsm4(bl,     base + 15360 + boff + kk * 32);
            ldsm4(bl + 4, base + 15360 + boff + 16 * 80 + kk * 32);
#pragma unroll
            for (int nt = 0; nt < 4; ++nt) {
                mma16816(acc[nt], ah, bh + 2 * nt);
                mma16816(acc[nt], ah, bl + 2 * nt);
                mma16816(acc[nt], al, bh + 2 * nt);
            }
        }
    }
#undef STAGE
    __syncthreads();   // both wgs done with their buffers before St staging

    // stage partial C to smem: wg0 -> St[0..4223], wg1 -> St[4224..8447]
    float* St = (float*)sm;
    float* Sw = St + wg * 4224;          // 64*66
    const int rr = wm + (lane >> 2);
#pragma unroll
    for (int nt = 0; nt < 4; ++nt) {
        int cc = wn + nt * 8 + ((lane & 3) << 1);
        Sw[cc * 66 + rr]           = acc[nt][0];
        Sw[(cc + 1) * 66 + rr]     = acc[nt][1];
        Sw[cc * 66 + rr + 8]       = acc[nt][2];
        Sw[(cc + 1) * 66 + rr + 8] = acc[nt][3];
    }
    __syncthreads();

    if (EPI == 0) {      // fused LSTM cell: cols = gate*16 + jj
#pragma unroll
        for (int it = 0; it < 2; ++it) {
            int idx = tx + it * 512;
            int b = idx & 63, jj = idx >> 6;          // jj 0..15
            int jg = nblk * 16 + jj;
            float gi = St[jj * 66 + b]        + St[4224 + jj * 66 + b];
            float gf = St[(16 + jj) * 66 + b] + St[4224 + (16 + jj) * 66 + b];
            float gg = St[(32 + jj) * 66 + b] + St[4224 + (32 + jj) * 66 + b];
            float go = St[(48 + jj) * 66 + b] + St[4224 + (48 + jj) * 66 + b];
            if (a.addC) {
                const float* ac = a.addC + (size_t)b * 4096 + jg;
                gi += ac[0]; gf += ac[1024]; gg += ac[2048]; go += ac[3072];
            }
            if (a.bias1) {
                gi += a.bias1[jg] + a.bias2[jg];
                gf += a.bias1[1024 + jg] + a.bias2[1024 + jg];
                gg += a.bias1[2048 + jg] + a.bias2[2048 + jg];
                go += a.bias1[3072 + jg] + a.bias2[3072 + jg];
            }
            float cc2 = sigm_(gf) * a.cSt[b * HH + jg] + sigm_(gi) * tanhf(gg);
            a.cSt[b * HH + jg] = cc2;
            float h = sigm_(go) * tanhf(cc2);
            a.hF[b * HH + jg] = h;
            split2(h, a.hH[b * HH + jg], a.hL[b * HH + jg]);
        }
    } else {             // plain store (optional bias / tanh)
#pragma unroll
        for (int it = 0; it < 8; ++it) {
            int idx = tx + it * 512;
            int row = idx >> 6, col = idx & 63;
            float v = St[col * 66 + row] + St[4224 + col * 66 + row];
            int cg = nblk * 64 + col;
            if (a.bias1) v += a.bias1[cg] + a.bias2[cg];
            if (a.doTanh) v = tanhf(v);
            a.outC[(size_t)(mblk * 64 + row) * a.ldC + cg] = v;
        }
    }
}

// ------------------------------ step kernel ----------------------------
struct StepP {
    int nL1, nOut, nL0, nQ, nAt;
    Seg l1, o, l0, q;
    const float *atQ, *atCtx;
    bf16 *atWcH, *atWcL;
    float* atP;
};

__global__ __launch_bounds__(512, 1) void step_k(StepP p) {
    extern __shared__ __align__(16) char sm[];
    const int bid = blockIdx.x;
    const int r0 = p.nL1, r1 = r0 + p.nOut, r2 = r1 + p.nL0, r3 = r2 + p.nQ;

    if (bid < r0) {
        mgemm<true, true, 0>(p.l1, sm, 0, bid);
    } else if (bid < r1) {
        mgemm<false, true, 1>(p.o, sm, 0, bid - r0);
    } else if (bid < r2) {
        mgemm<true, false, 0>(p.l0, sm, 0, bid - r1);
    } else if (bid < r3) {
        mgemm<false, false, 1>(p.q, sm, 0, bid - r2);
    } else {                              // ATTN: one block per batch b
        int b = bid - r3;
        float* qs = (float*)sm;           // 1024 floats
        float* sc = qs + 1024;            // 64 floats
        const int tx = threadIdx.x;
        *(float2*)&qs[tx * 2] = *(const float2*)&p.atQ[(size_t)b * HH + tx * 2];
        __syncthreads();
        const int wid = tx >> 5, lane = tx & 31;
        for (int s = wid; s < SS; s += 16) {
            const float* cp = p.atCtx + ((size_t)s * BB + b) * HH;
            float acc = 0.f;
#pragma unroll
            for (int i = 0; i < 8; ++i) {
                float4 c4 = *(const float4*)(cp + i * 128 + lane * 4);
                float4 q4 = *(const float4*)&qs[i * 128 + lane * 4];
                acc += c4.x * q4.x + c4.y * q4.y + c4.z * q4.z + c4.w * q4.w;
            }
#pragma unroll
            for (int o = 16; o; o >>= 1) acc += __shfl_down_sync(0xFFFFFFFFu, acc, o);
            if (lane == 0) sc[s] = acc;
        }
        __syncthreads();
        if (tx == 0) {
            float mx = sc[0];
            for (int s = 1; s < SS; ++s) mx = fmaxf(mx, sc[s]);
            float sum = 0.f;
            for (int s = 0; s < SS; ++s) { float e = expf(sc[s] - mx); sc[s] = e; sum += e; }
            float inv = 1.f / sum;
            for (int s = 0; s < SS; ++s) sc[s] *= inv;
        }
        __syncthreads();
        if (tx < SS) p.atP[b * SS + tx] = sc[tx];
        for (int k = tx; k < HH; k += 512) {
            float acc = 0.f;
#pragma unroll 8
            for (int s = 0; s < SS; ++s)
                acc += sc[s] * p.atCtx[((size_t)s * BB + b) * HH + k];
            split2(acc, p.atWcH[(size_t)b * HH + k], p.atWcL[(size_t)b * HH + k]);
        }
    }
}

// ---------------- X0 precompute: emb[input] @ w_ih0^T + biases ----------
__global__ __launch_bounds__(512, 1) void x0_k(StepP p) {
    extern __shared__ __align__(16) char sm[];
    mgemm<false, false, 1>(p.l0, sm, blockIdx.y, blockIdx.x);
}

// ----------------------------- init kernels ----------------------------
__global__ void split_w(const float* __restrict__ w_ih, const float* __restrict__ w_hh,
                        const float* __restrict__ w_in, const float* __restrict__ w_out) {
    const size_t N = 19922944;
    for (size_t i = (size_t)blockIdx.x * 256 + threadIdx.x; i < N;
         i += (size_t)gridDim.x * 256) {
        float v; bf16 *dh, *dl; size_t j;
        if (i < 8388608) {
            j = i; v = w_ih[j]; dh = g_Wih_h; dl = g_Wih_l;
        } else if (i < 16777216) {
            j = i - 8388608; v = w_hh[j]; dh = g_Whh_h; dl = g_Whh_l;
        } else if (i < 17825792) {
            j = i - 16777216; v = w_in[j]; dh = g_Win_h; dl = g_Win_l;
        } else {
            j = i - 17825792; v = w_out[j]; dh = g_Wo_h; dl = g_Wo_l;
        }
        split2(v, dh[j], dl[j]);
    }
}

__global__ void gather_xe(const int* __restrict__ inp, const float* __restrict__ emb) {
    size_t i = (size_t)blockIdx.x * 256 + threadIdx.x;
    if (i < 4194304) {
        size_t tb = i >> 10, k = i & 1023;
        float v = emb[(size_t)inp[tb] * 1024 + k];
        split2(v, g_XEh[i], g_XEl[i]);
    }
}

__global__ void init_sk(const float* __restrict__ h0, const float* __restrict__ c0) {
    int i = blockIdx.x * 256 + threadIdx.x;
    if (i < BH) {
        float a = h0[i], b = h0[BH + i];
        g_h0F[1][i] = a; split2(a, g_h0H[1][i], g_h0L[1][i]);   // h0(-1): slot 1
        g_h1F[3][i] = b; split2(b, g_h1H[3][i], g_h1L[3][i]);   // h1(-1): slot 3
        g_c0F[i] = c0[i];
        g_c1F[i] = c0[BH + i];
    }
}

__global__ void final_k(float* __restrict__ hf, float* __restrict__ cf,
                        float* __restrict__ at) {
    int i = blockIdx.x * 256 + threadIdx.x;
    if (i < BH) {
        hf[i] = g_h0F[1][i];            // h0(63): 63&1 = 1
        hf[BH + i] = g_h1F[3][i];       // h1(63): 63&3 = 3
        cf[i] = g_c0F[i];
        cf[BH + i] = g_c1F[i];
    }
    if (i < BB * SS) at[i] = g_attn[i];
}

// ------------------------------- launch --------------------------------
extern "C" void kernel_launch(void* const* d_in, const int* in_sizes, int n_in,
                              void* d_out, int out_size) {
    (void)in_sizes; (void)n_in; (void)out_size;
    const int*   inp   = (const int*)d_in[0];
    const float* h0    = (const float*)d_in[1];
    const float* c0    = (const float*)d_in[2];
    const float* ctx   = (const float*)d_in[3];
    const float* emb   = (const float*)d_in[4];
    const float* w_ih  = (const float*)d_in[5];
    const float* w_hh  = (const float*)d_in[6];
    const float* b_ih  = (const float*)d_in[7];
    const float* b_hh  = (const float*)d_in[8];
    const float* w_in  = (const float*)d_in[9];
    const float* w_out = (const float*)d_in[10];

    float* out  = (float*)d_out;
    float* outs = out;
    float* hf   = out + (size_t)TT * BH;
    float* cf   = hf + 2 * BH;
    float* at   = cf + 2 * BH;

    cudaFuncSetAttribute(step_k, cudaFuncAttributeMaxDynamicSharedMemorySize, SMB);
    cudaFuncSetAttribute(x0_k,   cudaFuncAttributeMaxDynamicSharedMemorySize, SMB);

    bf16 *WihH, *WihL, *WhhH, *WhhL, *WinH, *WinL, *WoH, *WoL, *XEh, *XEl;
    bf16 *h0H, *h0L, *h1H, *h1L, *wcH, *wcL;
    float *h0F, *h1F, *c0F, *c1F, *qF, *X0, *AT;
    cudaGetSymbolAddress((void**)&WihH, g_Wih_h); cudaGetSymbolAddress((void**)&WihL, g_Wih_l);
    cudaGetSymbolAddress((void**)&WhhH, g_Whh_h); cudaGetSymbolAddress((void**)&WhhL, g_Whh_l);
    cudaGetSymbolAddress((void**)&WinH, g_Win_h); cudaGetSymbolAddress((void**)&WinL, g_Win_l);
    cudaGetSymbolAddress((void**)&WoH,  g_Wo_h);  cudaGetSymbolAddress((void**)&WoL,  g_Wo_l);
    cudaGetSymbolAddress((void**)&XEh,  g_XEh);   cudaGetSymbolAddress((void**)&XEl,  g_XEl);
    cudaGetSymbolAddress((void**)&h0F, g_h0F); cudaGetSymbolAddress((void**)&h1F, g_h1F);
    cudaGetSymbolAddress((void**)&h0H, g_h0H); cudaGetSymbolAddress((void**)&h0L, g_h0L);
    cudaGetSymbolAddress((void**)&h1H, g_h1H); cudaGetSymbolAddress((void**)&h1L, g_h1L);
    cudaGetSymbolAddress((void**)&c0F, g_c0F); cudaGetSymbolAddress((void**)&c1F, g_c1F);
    cudaGetSymbolAddress((void**)&qF,  g_qF);
    cudaGetSymbolAddress((void**)&wcH, g_wcH); cudaGetSymbolAddress((void**)&wcL, g_wcL);
    cudaGetSymbolAddress((void**)&X0,  g_X0);
    cudaGetSymbolAddress((void**)&AT,  g_attn);

    split_w<<<16384, 256>>>(w_ih, w_hh, w_in, w_out);
    gather_xe<<<16384, 256>>>(inp, emb);
    init_sk<<<256, 256>>>(h0, c0);

    {   // X0 = XE @ w_ih0^T + b_ih0 + b_hh0, grid (64 nblk, 64 mblk)
        StepP p = {};
        Seg& s = p.l0;
        s.A1h = XEh; s.A1l = XEl;
        s.W1h = WihH; s.W1l = WihL; s.wld = 1024; s.K = 1024;
        s.bias1 = b_ih; s.bias2 = b_hh;
        s.outC = X0; s.ldC = 4096; s.doTanh = 0;
        x0_k<<<dim3(64, 64), 512, SMB>>>(p);
    }

    // Pipeline: launch k carries L1(k-1), OUT(k-4), L0(k), Q(k-2), ATTN(k-3).
    for (int k = 0; k <= 67; ++k) {
        StepP p = {};
        int tL1 = k - 1, tL0 = k, tQ = k - 2, tAt = k - 3, tOut = k - 4;
        if (tL1 >= 0 && tL1 < TT) {
            p.nL1 = 64;
            Seg& s = p.l1;
            s.A1h = h0H + (size_t)(tL1 & 1) * BH; s.A1l = h0L + (size_t)(tL1 & 1) * BH;
            s.A2h = h1H + (size_t)((tL1 - 1) & 3) * BH;
            s.A2l = h1L + (size_t)((tL1 - 1) & 3) * BH;
            s.W1h = WihH + 4194304; s.W1l = WihL + 4194304;
            s.W2h = WhhH + 4194304; s.W2l = WhhL + 4194304;
            s.wld = 1024; s.K = 2048;
            s.bias1 = b_ih + 4096; s.bias2 = b_hh + 4096;
            s.cSt = c1F;
            s.hF = h1F + (size_t)(tL1 & 3) * BH;
            s.hH = h1H + (size_t)(tL1 & 3) * BH;
            s.hL = h1L + (size_t)(tL1 & 3) * BH;
        }
        if (tOut >= 0 && tOut < TT) {
            p.nOut = 16;
            Seg& s = p.o;
            s.A1h = wcH + (size_t)(tOut & 1) * BH; s.A1l = wcL + (size_t)(tOut & 1) * BH;
            s.A2h = h1H + (size_t)(tOut & 3) * BH; s.A2l = h1L + (size_t)(tOut & 3) * BH;
            s.W1h = WoH; s.W1l = WoL;
            s.W2h = WoH + 1024; s.W2l = WoL + 1024;
            s.wld = 2048; s.K = 2048;
            s.outC = outs + (size_t)tOut * BH; s.ldC = HH; s.doTanh = 1;
        }
        if (tL0 >= 0 && tL0 < TT) {
            p.nL0 = 64;
            Seg& s = p.l0;
            s.A1h = h0H + (size_t)((tL0 + 1) & 1) * BH;
            s.A1l = h0L + (size_t)((tL0 + 1) & 1) * BH;
            s.W1h = WhhH; s.W1l = WhhL; s.wld = 1024; s.K = 1024;
            s.addC = X0 + (size_t)tL0 * 64 * 4096;
            s.cSt = c0F;
            s.hF = h0F + (size_t)(tL0 & 1) * BH;
            s.hH = h0H + (size_t)(tL0 & 1) * BH;
            s.hL = h0L + (size_t)(tL0 & 1) * BH;
        }
        if (tQ >= 0 && tQ < TT) {
            p.nQ = 16;
            Seg& s = p.q;
            s.A1h = h1H + (size_t)(tQ & 3) * BH; s.A1l = h1L + (size_t)(tQ & 3) * BH;
            s.W1h = WinH; s.W1l = WinL; s.wld = 1024; s.K = 1024;
            s.outC = qF + (size_t)(tQ & 1) * BH; s.ldC = HH; s.doTanh = 0;
        }
        if (tAt >= 0 && tAt < TT) {
            p.nAt = 64;
            p.atQ = qF + (size_t)(tAt & 1) * BH;
            p.atCtx = ctx;
            p.atWcH = wcH + (size_t)(tAt & 1) * BH;
            p.atWcL = wcL + (size_t)(tAt & 1) * BH;
            p.atP = AT;
        }
        int grid = p.nL1 + p.nOut + p.nL0 + p.nQ + p.nAt;
        if (grid > 0) step_k<<<grid, 512, SMB>>>(p);
    }

    final_k<<<512, 256>>>(hf, cf, at);
}

// round 9
// speedup vs baseline: 1.3879x; 1.0201x over previous
#include <cuda_runtime.h>
#include <cuda_bf16.h>
#include <cstdint>

// Decoder: 2-layer LSTM + Luong attention. T=B=S=64, H=E=1024, L=2.
// mma.sync bf16 (3-way split), 64x64 tiles, 512 threads = 4 warpgroups of
// 128 threads, 4-way K-split, k16 chunks, 4-stage cp.async pipeline.

#define TT 64
#define BB 64
#define SS 64
#define HH 1024
#define BH (BB * HH)

typedef unsigned long long ull;
typedef __nv_bfloat16 bf16;

__device__ __forceinline__ float sigm_(float x) { return 1.f / (1.f + expf(-x)); }
__device__ __forceinline__ void split2(float v, bf16& hi, bf16& lo) {
    hi = __float2bfloat16(v);
    lo = __float2bfloat16(v - __bfloat162float(hi));
}

// ------------------------------- scratch -------------------------------
__device__ __align__(256) bf16 g_Wih_h[8388608], g_Wih_l[8388608];
__device__ __align__(256) bf16 g_Whh_h[8388608], g_Whh_l[8388608];
__device__ __align__(256) bf16 g_Win_h[1048576], g_Win_l[1048576];
__device__ __align__(256) bf16 g_Wo_h[2097152],  g_Wo_l[2097152];
__device__ __align__(256) bf16 g_XEh[4194304],   g_XEl[4194304];
__device__ float g_X0[(size_t)4096 * 4096];        // [t*64+b][4096 gate cols]
__device__ float g_h0F[2][BH], g_h1F[4][BH], g_c0F[BH], g_c1F[BH];
__device__ __align__(256) bf16 g_h0H[2][BH], g_h0L[2][BH];
__device__ __align__(256) bf16 g_h1H[4][BH], g_h1L[4][BH];
__device__ __align__(256) bf16 g_wcH[2][BH], g_wcL[2][BH];
__device__ float g_qF[2][BH];
__device__ float g_attn[BB * SS];

// ----------------------------- ptx helpers -----------------------------
__device__ __forceinline__ uint32_t s2u(const void* p) {
    uint32_t a;
    asm("{ .reg .u64 t; cvta.to.shared.u64 t, %1; cvt.u32.u64 %0, t; }"
        : "=r"(a) : "l"(p));
    return a;
}
__device__ __forceinline__ void cpa16(uint32_t dst, const void* src) {
    asm volatile("cp.async.cg.shared.global [%0], [%1], 16;"
                 :: "r"(dst), "l"(src) : "memory");
}
__device__ __forceinline__ void ldsm4(uint32_t* r, uint32_t addr) {
    asm volatile("ldmatrix.sync.aligned.m8n8.x4.shared.b16 {%0,%1,%2,%3}, [%4];"
                 : "=r"(r[0]), "=r"(r[1]), "=r"(r[2]), "=r"(r[3]) : "r"(addr));
}
__device__ __forceinline__ void mma16816(float* d, const uint32_t* a, const uint32_t* b) {
    asm volatile(
        "mma.sync.aligned.m16n8k16.row.col.f32.bf16.bf16.f32 "
        "{%0,%1,%2,%3},{%4,%5,%6,%7},{%8,%9},{%0,%1,%2,%3};"
        : "+f"(d[0]), "+f"(d[1]), "+f"(d[2]), "+f"(d[3])
        : "r"(a[0]), "r"(a[1]), "r"(a[2]), "r"(a[3]), "r"(b[0]), "r"(b[1]));
}
__device__ __forceinline__ void barw(int wg) {
    asm volatile("bar.sync %0, 128;" :: "r"(wg + 1) : "memory");
}

// ---------------------------- GEMM segment -----------------------------
// C[64 m(batch), 64 n] = A @ W^T. 512 threads = 4 wgs of 128; each wg does
// a K/4 slice into its own partial accumulator; combined in epilogue.
// GATE: n cols = 4 gates x 16 hidden units. PAIR2: K=2048 (wg pair = half).
struct Seg {
    const bf16 *A1h, *A1l, *A2h, *A2l;
    const bf16 *W1h, *W1l, *W2h, *W2l;
    int wld, K;
    const float *addC, *bias1, *bias2;
    float *cSt, *hF;
    bf16 *hH, *hL;
    float *outC; int ldC, doTanh;
};

// per-wg stage (k16): Ah 3072 | Al 3072 | Wh 3072 | Wl 3072 = 12288 B
// (rows 64 x 48B: 32B data + 16B pad -> conflict-free ldsm).
// 4 stages/wg x 4 wg = 196608 B dynamic smem.
#define STGB 12288
#define WGB (4 * STGB)
#define SMB (4 * WGB)

template <bool GATE, bool PAIR2, int EPI>
__device__ void mgemm(const Seg& a, char* sm, int mblk, int nblk) {
    const int tx = threadIdx.x;
    const int wg = tx >> 7;              // warpgroup 0..3
    const int wtx = tx & 127;
    const int warp = wtx >> 5, lane = tx & 31;
    const int wm = warp << 4;            // warp m offset 0..48 (n covers all 64)
    const uint32_t smb = s2u(sm) + wg * WGB;

    // staging: thread -> (row 0..63, 16B unit 0..1)
    const int sr = wtx >> 1, su = wtx & 1;
    const int am = mblk * 64 + sr;
    const int wr = GATE ? ((sr >> 4) * HH + nblk * 16 + (sr & 15))
                        : (nblk * 64 + sr);

    // per-wg operands and K range
    const bf16 *a1, *a2, *w1, *w2;
    int kbase, Kwg;
    if (PAIR2) {
        int p = wg >> 1;
        a1 = p ? a.A2h : a.A1h; a2 = p ? a.A2l : a.A1l;
        w1 = p ? a.W2h : a.W1h; w2 = p ? a.W2l : a.W1l;
        kbase = (wg & 1) << 9; Kwg = 512;
    } else {
        a1 = a.A1h; a2 = a.A1l; w1 = a.W1h; w2 = a.W1l;
        Kwg = a.K >> 2; kbase = wg * Kwg;
    }
    const size_t arow = (size_t)am * 1024;
    const size_t wrow = (size_t)wr * a.wld;

    float acc[8][4] = {};
    const int nc = Kwg >> 4;             // k16 chunks

    const uint32_t aoff = (uint32_t)((wm + (lane & 15)) * 48 + ((lane >> 4) << 4));
    const uint32_t boff = (uint32_t)(((((lane >> 4) << 3) + (lane & 7))) * 48
                                     + (((lane >> 3) & 1) << 4));

#define STAGE(c)                                                               \
    {                                                                          \
        int kl = kbase + ((c) << 4);                                           \
        uint32_t db = smb + ((c) & 3) * STGB + sr * 48 + (su << 4);            \
        size_t ao = arow + kl + su * 8;                                        \
        size_t wo = wrow + kl + su * 8;                                        \
        cpa16(db,        a1 + ao);                                             \
        cpa16(db + 3072, a2 + ao);                                             \
        cpa16(db + 6144, w1 + wo);                                             \
        cpa16(db + 9216, w2 + wo);                                             \
        asm volatile("cp.async.commit_group;" ::: "memory");                   \
    }

    STAGE(0) STAGE(1) STAGE(2)
    for (int c = 0; c < nc; ++c) {
        if (c + 3 < nc) {
            asm volatile("cp.async.wait_group 2;" ::: "memory");
            barw(wg);
            STAGE(c + 3)
        } else {
            asm volatile("cp.async.wait_group 0;" ::: "memory");
            barw(wg);
        }
        const uint32_t base = smb + (c & 3) * STGB;
        uint32_t ah[4], al[4], bh[16], bl[16];
        ldsm4(ah, base + aoff);
        ldsm4(al, base + 3072 + aoff);
#pragma unroll
        for (int j = 0; j < 4; ++j) {
            ldsm4(bh + 4 * j, base + 6144 + boff + j * 16 * 48);
            ldsm4(bl + 4 * j, base + 9216 + boff + j * 16 * 48);
        }
#pragma unroll
        for (int nt = 0; nt < 8; ++nt) {
            mma16816(acc[nt], ah, bh + 2 * nt);
            mma16816(acc[nt], ah, bl + 2 * nt);
            mma16816(acc[nt], al, bh + 2 * nt);
        }
    }
#undef STAGE
    __syncthreads();   // all wgs done with buffers before St staging

    // stage partial C: wg i -> St[i*4224 ..]
    float* St = (float*)sm;
    float* Sw = St + wg * 4224;          // 64*66
    const int rr = wm + (lane >> 2);
#pragma unroll
    for (int nt = 0; nt < 8; ++nt) {
        int cc = nt * 8 + ((lane & 3) << 1);
        Sw[cc * 66 + rr]           = acc[nt][0];
        Sw[(cc + 1) * 66 + rr]     = acc[nt][1];
        Sw[cc * 66 + rr + 8]       = acc[nt][2];
        Sw[(cc + 1) * 66 + rr + 8] = acc[nt][3];
    }
    __syncthreads();

    if (EPI == 0) {      // fused LSTM cell: cols = gate*16 + jj
#pragma unroll
        for (int it = 0; it < 2; ++it) {
            int idx = tx + it * 512;
            int b = idx & 63, jj = idx >> 6;          // jj 0..15
            int jg = nblk * 16 + jj;
            float gi = St[jj * 66 + b]        + St[4224 + jj * 66 + b]
                     + St[8448 + jj * 66 + b] + St[12672 + jj * 66 + b];
            float gf = St[(16 + jj) * 66 + b]        + St[4224 + (16 + jj) * 66 + b]
                     + St[8448 + (16 + jj) * 66 + b] + St[12672 + (16 + jj) * 66 + b];
            float gg = St[(32 + jj) * 66 + b]        + St[4224 + (32 + jj) * 66 + b]
                     + St[8448 + (32 + jj) * 66 + b] + St[12672 + (32 + jj) * 66 + b];
            float go = St[(48 + jj) * 66 + b]        + St[4224 + (48 + jj) * 66 + b]
                     + St[8448 + (48 + jj) * 66 + b] + St[12672 + (48 + jj) * 66 + b];
            if (a.addC) {
                const float* ac = a.addC + (size_t)b * 4096 + jg;
                gi += ac[0]; gf += ac[1024]; gg += ac[2048]; go += ac[3072];
            }
            if (a.bias1) {
                gi += a.bias1[jg] + a.bias2[jg];
                gf += a.bias1[1024 + jg] + a.bias2[1024 + jg];
                gg += a.bias1[2048 + jg] + a.bias2[2048 + jg];
                go += a.bias1[3072 + jg] + a.bias2[3072 + jg];
            }
            float cc2 = sigm_(gf) * a.cSt[b * HH + jg] + sigm_(gi) * tanhf(gg);
            a.cSt[b * HH + jg] = cc2;
            float h = sigm_(go) * tanhf(cc2);
            a.hF[b * HH + jg] = h;
            split2(h, a.hH[b * HH + jg], a.hL[b * HH + jg]);
        }
    } else {             // plain store (optional bias / tanh)
#pragma unroll
        for (int it = 0; it < 8; ++it) {
            int idx = tx + it * 512;
            int row = idx >> 6, col = idx & 63;
            float v = St[col * 66 + row]        + St[4224 + col * 66 + row]
                    + St[8448 + col * 66 + row] + St[12672 + col * 66 + row];
            int cg = nblk * 64 + col;
            if (a.bias1) v += a.bias1[cg] + a.bias2[cg];
            if (a.doTanh) v = tanhf(v);
            a.outC[(size_t)(mblk * 64 + row) * a.ldC + cg] = v;
        }
    }
}

// ------------------------------ step kernel ----------------------------
struct StepP {
    int nL1, nOut, nL0, nQ, nAt;
    Seg l1, o, l0, q;
    const float *atQ, *atCtx;
    bf16 *atWcH, *atWcL;
    float* atP;
};

__global__ __launch_bounds__(512, 1) void step_k(StepP p) {
    extern __shared__ __align__(16) char sm[];
    const int bid = blockIdx.x;
    const int r0 = p.nL1, r1 = r0 + p.nOut, r2 = r1 + p.nL0, r3 = r2 + p.nQ;

    if (bid < r0) {
        mgemm<true, true, 0>(p.l1, sm, 0, bid);
    } else if (bid < r1) {
        mgemm<false, true, 1>(p.o, sm, 0, bid - r0);
    } else if (bid < r2) {
        mgemm<true, false, 0>(p.l0, sm, 0, bid - r1);
    } else if (bid < r3) {
        mgemm<false, false, 1>(p.q, sm, 0, bid - r2);
    } else {                              // ATTN: one block per batch b
        int b = bid - r3;
        float* qs = (float*)sm;           // 1024 floats
        float* sc = qs + 1024;            // 64 floats
        const int tx = threadIdx.x;
        *(float2*)&qs[tx * 2] = *(const float2*)&p.atQ[(size_t)b * HH + tx * 2];
        __syncthreads();
        const int wid = tx >> 5, lane = tx & 31;
        for (int s = wid; s < SS; s += 16) {
            const float* cp = p.atCtx + ((size_t)s * BB + b) * HH;
            float acc = 0.f;
#pragma unroll
            for (int i = 0; i < 8; ++i) {
                float4 c4 = *(const float4*)(cp + i * 128 + lane * 4);
                float4 q4 = *(const float4*)&qs[i * 128 + lane * 4];
                acc += c4.x * q4.x + c4.y * q4.y + c4.z * q4.z + c4.w * q4.w;
            }
#pragma unroll
            for (int o = 16; o; o >>= 1) acc += __shfl_down_sync(0xFFFFFFFFu, acc, o);
            if (lane == 0) sc[s] = acc;
        }
        __syncthreads();
        if (tx == 0) {
            float mx = sc[0];
            for (int s = 1; s < SS; ++s) mx = fmaxf(mx, sc[s]);
            float sum = 0.f;
            for (int s = 0; s < SS; ++s) { float e = expf(sc[s] - mx); sc[s] = e; sum += e; }
            float inv = 1.f / sum;
            for (int s = 0; s < SS; ++s) sc[s] *= inv;
        }
        __syncthreads();
        if (tx < SS) p.atP[b * SS + tx] = sc[tx];
        for (int k = tx; k < HH; k += 512) {
            float acc = 0.f;
#pragma unroll 8
            for (int s = 0; s < SS; ++s)
                acc += sc[s] * p.atCtx[((size_t)s * BB + b) * HH + k];
            split2(acc, p.atWcH[(size_t)b * HH + k], p.atWcL[(size_t)b * HH + k]);
        }
    }
}

// ---------------- X0 precompute: emb[input] @ w_ih0^T + biases ----------
__global__ __launch_bounds__(512, 1) void x0_k(StepP p) {
    extern __shared__ __align__(16) char sm[];
    mgemm<false, false, 1>(p.l0, sm, blockIdx.y, blockIdx.x);
}

// ----------------------------- init kernels ----------------------------
__global__ void split_w(const float* __restrict__ w_ih, const float* __restrict__ w_hh,
                        const float* __restrict__ w_in, const float* __restrict__ w_out) {
    const size_t N = 19922944;
    for (size_t i = (size_t)blockIdx.x * 256 + threadIdx.x; i < N;
         i += (size_t)gridDim.x * 256) {
        float v; bf16 *dh, *dl; size_t j;
        if (i < 8388608) {
            j = i; v = w_ih[j]; dh = g_Wih_h; dl = g_Wih_l;
        } else if (i < 16777216) {
            j = i - 8388608; v = w_hh[j]; dh = g_Whh_h; dl = g_Whh_l;
        } else if (i < 17825792) {
            j = i - 16777216; v = w_in[j]; dh = g_Win_h; dl = g_Win_l;
        } else {
            j = i - 17825792; v = w_out[j]; dh = g_Wo_h; dl = g_Wo_l;
        }
        split2(v, dh[j], dl[j]);
    }
}

__global__ void gather_xe(const int* __restrict__ inp, const float* __restrict__ emb) {
    size_t i = (size_t)blockIdx.x * 256 + threadIdx.x;
    if (i < 4194304) {
        size_t tb = i >> 10, k = i & 1023;
        float v = emb[(size_t)inp[tb] * 1024 + k];
        split2(v, g_XEh[i], g_XEl[i]);
    }
}

__global__ void init_sk(const float* __restrict__ h0, const float* __restrict__ c0) {
    int i = blockIdx.x * 256 + threadIdx.x;
    if (i < BH) {
        float a = h0[i], b = h0[BH + i];
        g_h0F[1][i] = a; split2(a, g_h0H[1][i], g_h0L[1][i]);   // h0(-1): slot 1
        g_h1F[3][i] = b; split2(b, g_h1H[3][i], g_h1L[3][i]);   // h1(-1): slot 3
        g_c0F[i] = c0[i];
        g_c1F[i] = c0[BH + i];
    }
}

__global__ void final_k(float* __restrict__ hf, float* __restrict__ cf,
                        float* __restrict__ at) {
    int i = blockIdx.x * 256 + threadIdx.x;
    if (i < BH) {
        hf[i] = g_h0F[1][i];            // h0(63): 63&1 = 1
        hf[BH + i] = g_h1F[3][i];       // h1(63): 63&3 = 3
        cf[i] = g_c0F[i];
        cf[BH + i] = g_c1F[i];
    }
    if (i < BB * SS) at[i] = g_attn[i];
}

// ------------------------------- launch --------------------------------
extern "C" void kernel_launch(void* const* d_in, const int* in_sizes, int n_in,
                              void* d_out, int out_size) {
    (void)in_sizes; (void)n_in; (void)out_size;
    const int*   inp   = (const int*)d_in[0];
    const float* h0    = (const float*)d_in[1];
    const float* c0    = (const float*)d_in[2];
    const float* ctx   = (const float*)d_in[3];
    const float* emb   = (const float*)d_in[4];
    const float* w_ih  = (const float*)d_in[5];
    const float* w_hh  = (const float*)d_in[6];
    const float* b_ih  = (const float*)d_in[7];
    const float* b_hh  = (const float*)d_in[8];
    const float* w_in  = (const float*)d_in[9];
    const float* w_out = (const float*)d_in[10];

    float* out  = (float*)d_out;
    float* outs = out;
    float* hf   = out + (size_t)TT * BH;
    float* cf   = hf + 2 * BH;
    float* at   = cf + 2 * BH;

    cudaFuncSetAttribute(step_k, cudaFuncAttributeMaxDynamicSharedMemorySize, SMB);
    cudaFuncSetAttribute(x0_k,   cudaFuncAttributeMaxDynamicSharedMemorySize, SMB);

    bf16 *WihH, *WihL, *WhhH, *WhhL, *WinH, *WinL, *WoH, *WoL, *XEh, *XEl;
    bf16 *h0H, *h0L, *h1H, *h1L, *wcH, *wcL;
    float *h0F, *h1F, *c0F, *c1F, *qF, *X0, *AT;
    cudaGetSymbolAddress((void**)&WihH, g_Wih_h); cudaGetSymbolAddress((void**)&WihL, g_Wih_l);
    cudaGetSymbolAddress((void**)&WhhH, g_Whh_h); cudaGetSymbolAddress((void**)&WhhL, g_Whh_l);
    cudaGetSymbolAddress((void**)&WinH, g_Win_h); cudaGetSymbolAddress((void**)&WinL, g_Win_l);
    cudaGetSymbolAddress((void**)&WoH,  g_Wo_h);  cudaGetSymbolAddress((void**)&WoL,  g_Wo_l);
    cudaGetSymbolAddress((void**)&XEh,  g_XEh);   cudaGetSymbolAddress((void**)&XEl,  g_XEl);
    cudaGetSymbolAddress((void**)&h0F, g_h0F); cudaGetSymbolAddress((void**)&h1F, g_h1F);
    cudaGetSymbolAddress((void**)&h0H, g_h0H); cudaGetSymbolAddress((void**)&h0L, g_h0L);
    cudaGetSymbolAddress((void**)&h1H, g_h1H); cudaGetSymbolAddress((void**)&h1L, g_h1L);
    cudaGetSymbolAddress((void**)&c0F, g_c0F); cudaGetSymbolAddress((void**)&c1F, g_c1F);
    cudaGetSymbolAddress((void**)&qF,  g_qF);
    cudaGetSymbolAddress((void**)&wcH, g_wcH); cudaGetSymbolAddress((void**)&wcL, g_wcL);
    cudaGetSymbolAddress((void**)&X0,  g_X0);
    cudaGetSymbolAddress((void**)&AT,  g_attn);

    split_w<<<16384, 256>>>(w_ih, w_hh, w_in, w_out);
    gather_xe<<<16384, 256>>>(inp, emb);
    init_sk<<<256, 256>>>(h0, c0);

    {   // X0 = XE @ w_ih0^T + b_ih0 + b_hh0, grid (64 nblk, 64 mblk)
        StepP p = {};
        Seg& s = p.l0;
        s.A1h = XEh; s.A1l = XEl;
        s.W1h = WihH; s.W1l = WihL; s.wld = 1024; s.K = 1024;
        s.bias1 = b_ih; s.bias2 = b_hh;
        s.outC = X0; s.ldC = 4096; s.doTanh = 0;
        x0_k<<<dim3(64, 64), 512, SMB>>>(p);
    }

    // Pipeline: launch k carries L1(k-1), OUT(k-4), L0(k), Q(k-2), ATTN(k-3).
    for (int k = 0; k <= 67; ++k) {
        StepP p = {};
        int tL1 = k - 1, tL0 = k, tQ = k - 2, tAt = k - 3, tOut = k - 4;
        if (tL1 >= 0 && tL1 < TT) {
            p.nL1 = 64;
            Seg& s = p.l1;
            s.A1h = h0H + (size_t)(tL1 & 1) * BH; s.A1l = h0L + (size_t)(tL1 & 1) * BH;
            s.A2h = h1H + (size_t)((tL1 - 1) & 3) * BH;
            s.A2l = h1L + (size_t)((tL1 - 1) & 3) * BH;
            s.W1h = WihH + 4194304; s.W1l = WihL + 4194304;
            s.W2h = WhhH + 4194304; s.W2l = WhhL + 4194304;
            s.wld = 1024; s.K = 2048;
            s.bias1 = b_ih + 4096; s.bias2 = b_hh + 4096;
            s.cSt = c1F;
            s.hF = h1F + (size_t)(tL1 & 3) * BH;
            s.hH = h1H + (size_t)(tL1 & 3) * BH;
            s.hL = h1L + (size_t)(tL1 & 3) * BH;
        }
        if (tOut >= 0 && tOut < TT) {
            p.nOut = 16;
            Seg& s = p.o;
            s.A1h = wcH + (size_t)(tOut & 1) * BH; s.A1l = wcL + (size_t)(tOut & 1) * BH;
            s.A2h = h1H + (size_t)(tOut & 3) * BH; s.A2l = h1L + (size_t)(tOut & 3) * BH;
            s.W1h = WoH; s.W1l = WoL;
            s.W2h = WoH + 1024; s.W2l = WoL + 1024;
            s.wld = 2048; s.K = 2048;
            s.outC = outs + (size_t)tOut * BH; s.ldC = HH; s.doTanh = 1;
        }
        if (tL0 >= 0 && tL0 < TT) {
            p.nL0 = 64;
            Seg& s = p.l0;
            s.A1h = h0H + (size_t)((tL0 + 1) & 1) * BH;
            s.A1l = h0L + (size_t)((tL0 + 1) & 1) * BH;
            s.W1h = WhhH; s.W1l = WhhL; s.wld = 1024; s.K = 1024;
            s.addC = X0 + (size_t)tL0 * 64 * 4096;
            s.cSt = c0F;
            s.hF = h0F + (size_t)(tL0 & 1) * BH;
            s.hH = h0H + (size_t)(tL0 & 1) * BH;
            s.hL = h0L + (size_t)(tL0 & 1) * BH;
        }
        if (tQ >= 0 && tQ < TT) {
            p.nQ = 16;
            Seg& s = p.q;
            s.A1h = h1H + (size_t)(tQ & 3) * BH; s.A1l = h1L + (size_t)(tQ & 3) * BH;
            s.W1h = WinH; s.W1l = WinL; s.wld = 1024; s.K = 1024;
            s.outC = qF + (size_t)(tQ & 1) * BH; s.ldC = HH; s.doTanh = 0;
        }
        if (tAt >= 0 && tAt < TT) {
            p.nAt = 64;
            p.atQ = qF + (size_t)(tAt & 1) * BH;
            p.atCtx = ctx;
            p.atWcH = wcH + (size_t)(tAt & 1) * BH;
            p.atWcL = wcL + (size_t)(tAt & 1) * BH;
            p.atP = AT;
        }
        int grid = p.nL1 + p.nOut + p.nL0 + p.nQ + p.nAt;
        if (grid > 0) step_k<<<grid, 512, SMB>>>(p);
    }

    final_k<<<512, 256>>>(hf, cf, at);
}

// round 10
// speedup vs baseline: 1.6438x; 1.1844x over previous
#include <cuda_runtime.h>
#include <cuda_fp16.h>
#include <cstdint>

// Decoder: 2-layer LSTM + Luong attention. T=B=S=64, H=E=1024, L=2.
// mma.sync fp16 (A hi/lo 2-term split, W single fp16), 64x64 tiles,
// 512 threads = 4 warpgroups, 4-way K-split, k16 chunks, 4-stage pipeline.
// Block order per launch balanced for per-SM L2 traffic.

#define TT 64
#define BB 64
#define SS 64
#define HH 1024
#define BH (BB * HH)

typedef unsigned long long ull;
typedef __half h16;

__device__ __forceinline__ float sigm_(float x) { return 1.f / (1.f + expf(-x)); }
__device__ __forceinline__ void split2(float v, h16& hi, h16& lo) {
    hi = __float2half_rn(v);
    lo = __float2half_rn(v - __half2float(hi));
}

// ------------------------------- scratch -------------------------------
__device__ __align__(256) h16 g_Wih[8388608];      // [2][4096][1024]
__device__ __align__(256) h16 g_Whh[8388608];
__device__ __align__(256) h16 g_Win[1048576];
__device__ __align__(256) h16 g_Wo[2097152];       // [1024][2048]
__device__ __align__(256) h16 g_XEh[4194304], g_XEl[4194304];
__device__ float g_X0[(size_t)4096 * 4096];        // [t*64+b][4096 gate cols]
__device__ float g_h0F[2][BH], g_h1F[4][BH], g_c0F[BH], g_c1F[BH];
__device__ __align__(256) h16 g_h0H[2][BH], g_h0L[2][BH];
__device__ __align__(256) h16 g_h1H[4][BH], g_h1L[4][BH];
__device__ __align__(256) h16 g_wcH[2][BH], g_wcL[2][BH];
__device__ float g_qF[2][BH];
__device__ float g_attn[BB * SS];

// ----------------------------- ptx helpers -----------------------------
__device__ __forceinline__ uint32_t s2u(const void* p) {
    uint32_t a;
    asm("{ .reg .u64 t; cvta.to.shared.u64 t, %1; cvt.u32.u64 %0, t; }"
        : "=r"(a) : "l"(p));
    return a;
}
__device__ __forceinline__ void cpa16(uint32_t dst, const void* src) {
    asm volatile("cp.async.cg.shared.global [%0], [%1], 16;"
                 :: "r"(dst), "l"(src) : "memory");
}
__device__ __forceinline__ void ldsm4(uint32_t* r, uint32_t addr) {
    asm volatile("ldmatrix.sync.aligned.m8n8.x4.shared.b16 {%0,%1,%2,%3}, [%4];"
                 : "=r"(r[0]), "=r"(r[1]), "=r"(r[2]), "=r"(r[3]) : "r"(addr));
}
__device__ __forceinline__ void mma16816(float* d, const uint32_t* a, const uint32_t* b) {
    asm volatile(
        "mma.sync.aligned.m16n8k16.row.col.f32.f16.f16.f32 "
        "{%0,%1,%2,%3},{%4,%5,%6,%7},{%8,%9},{%0,%1,%2,%3};"
        : "+f"(d[0]), "+f"(d[1]), "+f"(d[2]), "+f"(d[3])
        : "r"(a[0]), "r"(a[1]), "r"(a[2]), "r"(a[3]), "r"(b[0]), "r"(b[1]));
}
__device__ __forceinline__ void barw(int wg) {
    asm volatile("bar.sync %0, 128;" :: "r"(wg + 1) : "memory");
}

// ---------------------------- GEMM segment -----------------------------
// C[64 m(batch), 64 n] = A @ W^T. 512 threads = 4 wgs of 128; each wg does
// a K/4 slice into a partial accumulator; combined in epilogue.
// A is fp16 hi/lo (2-term split); W is single fp16.
// GATE: n cols = 4 gates x 16 hidden units. PAIR2: K=2048 (wg pair = half).
struct Seg {
    const h16 *A1h, *A1l, *A2h, *A2l;
    const h16 *W1, *W2;
    int wld, K;
    const float *addC, *bias1, *bias2;
    float *cSt, *hF;
    h16 *hH, *hL;
    float *outC; int ldC, doTanh;
};

// per-wg stage (k16): Ah 3072 | Al 3072 | W 3072 = 9216 B
// (rows 64 x 48B: 32B data + 16B pad -> conflict-free ldsm).
// 4 stages/wg x 4 wg = 147456 B dynamic smem.
#define STGB 9216
#define WGB (4 * STGB)
#define SMB (4 * WGB)

template <bool GATE, bool PAIR2, int EPI>
__device__ void mgemm(const Seg& a, char* sm, int mblk, int nblk) {
    const int tx = threadIdx.x;
    const int wg = tx >> 7;              // warpgroup 0..3
    const int wtx = tx & 127;
    const int warp = wtx >> 5, lane = tx & 31;
    const int wm = warp << 4;            // warp m offset; n covers all 64
    const uint32_t smb = s2u(sm) + wg * WGB;

    // staging: thread -> (row 0..63, 16B unit 0..1)
    const int sr = wtx >> 1, su = wtx & 1;
    const int am = mblk * 64 + sr;
    const int wr = GATE ? ((sr >> 4) * HH + nblk * 16 + (sr & 15))
                        : (nblk * 64 + sr);

    // per-wg operands and K range
    const h16 *a1, *a2, *w1;
    int kbase, Kwg;
    if (PAIR2) {
        int p = wg >> 1;
        a1 = p ? a.A2h : a.A1h; a2 = p ? a.A2l : a.A1l;
        w1 = p ? a.W2 : a.W1;
        kbase = (wg & 1) << 9; Kwg = 512;
    } else {
        a1 = a.A1h; a2 = a.A1l; w1 = a.W1;
        Kwg = a.K >> 2; kbase = wg * Kwg;
    }
    const size_t arow = (size_t)am * 1024;
    const size_t wrow = (size_t)wr * a.wld;

    float acc[8][4] = {};
    const int nc = Kwg >> 4;             // k16 chunks

    const uint32_t aoff = (uint32_t)((wm + (lane & 15)) * 48 + ((lane >> 4) << 4));
    const uint32_t boff = (uint32_t)(((((lane >> 4) << 3) + (lane & 7))) * 48
                                     + (((lane >> 3) & 1) << 4));

#define STAGE(c)                                                               \
    {                                                                          \
        int kl = kbase + ((c) << 4);                                           \
        uint32_t db = smb + ((c) & 3) * STGB + sr * 48 + (su << 4);            \
        cpa16(db,        a1 + arow + kl + su * 8);                             \
        cpa16(db + 3072, a2 + arow + kl + su * 8);                             \
        cpa16(db + 6144, w1 + wrow + kl + su * 8);                             \
        asm volatile("cp.async.commit_group;" ::: "memory");                   \
    }

    STAGE(0) STAGE(1) STAGE(2)
    for (int c = 0; c < nc; ++c) {
        if (c + 3 < nc) {
            asm volatile("cp.async.wait_group 2;" ::: "memory");
            barw(wg);
            STAGE(c + 3)
        } else {
            asm volatile("cp.async.wait_group 0;" ::: "memory");
            barw(wg);
        }
        const uint32_t base = smb + (c & 3) * STGB;
        uint32_t ah[4], al[4], bw[16];
        ldsm4(ah, base + aoff);
        ldsm4(al, base + 3072 + aoff);
#pragma unroll
        for (int j = 0; j < 4; ++j)
            ldsm4(bw + 4 * j, base + 6144 + boff + j * 16 * 48);
#pragma unroll
        for (int nt = 0; nt < 8; ++nt) {
            mma16816(acc[nt], ah, bw + 2 * nt);
            mma16816(acc[nt], al, bw + 2 * nt);
        }
    }
#undef STAGE
    __syncthreads();   // all wgs done with buffers before St staging

    // stage partial C: wg i -> St[i*4224 ..]
    float* St = (float*)sm;
    float* Sw = St + wg * 4224;          // 64*66
    const int rr = wm + (lane >> 2);
#pragma unroll
    for (int nt = 0; nt < 8; ++nt) {
        int cc = nt * 8 + ((lane & 3) << 1);
        Sw[cc * 66 + rr]           = acc[nt][0];
        Sw[(cc + 1) * 66 + rr]     = acc[nt][1];
        Sw[cc * 66 + rr + 8]       = acc[nt][2];
        Sw[(cc + 1) * 66 + rr + 8] = acc[nt][3];
    }
    __syncthreads();

    if (EPI == 0) {      // fused LSTM cell: cols = gate*16 + jj
#pragma unroll
        for (int it = 0; it < 2; ++it) {
            int idx = tx + it * 512;
            int b = idx & 63, jj = idx >> 6;          // jj 0..15
            int jg = nblk * 16 + jj;
            float gi = St[jj * 66 + b]        + St[4224 + jj * 66 + b]
                     + St[8448 + jj * 66 + b] + St[12672 + jj * 66 + b];
            float gf = St[(16 + jj) * 66 + b]        + St[4224 + (16 + jj) * 66 + b]
                     + St[8448 + (16 + jj) * 66 + b] + St[12672 + (16 + jj) * 66 + b];
            float gg = St[(32 + jj) * 66 + b]        + St[4224 + (32 + jj) * 66 + b]
                     + St[8448 + (32 + jj) * 66 + b] + St[12672 + (32 + jj) * 66 + b];
            float go = St[(48 + jj) * 66 + b]        + St[4224 + (48 + jj) * 66 + b]
                     + St[8448 + (48 + jj) * 66 + b] + St[12672 + (48 + jj) * 66 + b];
            if (a.addC) {
                const float* ac = a.addC + (size_t)b * 4096 + jg;
                gi += ac[0]; gf += ac[1024]; gg += ac[2048]; go += ac[3072];
            }
            if (a.bias1) {
                gi += a.bias1[jg] + a.bias2[jg];
                gf += a.bias1[1024 + jg] + a.bias2[1024 + jg];
                gg += a.bias1[2048 + jg] + a.bias2[2048 + jg];
                go += a.bias1[3072 + jg] + a.bias2[3072 + jg];
            }
            float cc2 = sigm_(gf) * a.cSt[b * HH + jg] + sigm_(gi) * tanhf(gg);
            a.cSt[b * HH + jg] = cc2;
            float h = sigm_(go) * tanhf(cc2);
            a.hF[b * HH + jg] = h;
            split2(h, a.hH[b * HH + jg], a.hL[b * HH + jg]);
        }
    } else {             // plain store (optional bias / tanh)
#pragma unroll
        for (int it = 0; it < 8; ++it) {
            int idx = tx + it * 512;
            int row = idx >> 6, col = idx & 63;
            float v = St[col * 66 + row]        + St[4224 + col * 66 + row]
                    + St[8448 + col * 66 + row] + St[12672 + col * 66 + row];
            int cg = nblk * 64 + col;
            if (a.bias1) v += a.bias1[cg] + a.bias2[cg];
            if (a.doTanh) v = tanhf(v);
            a.outC[(size_t)(mblk * 64 + row) * a.ldC + cg] = v;
        }
    }
}

// ------------------------------ step kernel ----------------------------
// Block order (L2-traffic balance with bid/bid+148 SM pairing):
//   [ATTN, OUT, L1, L0, Q] -- heavy L1 sits in single-block bid range.
struct StepP {
    int nL1, nOut, nL0, nQ, nAt;
    Seg l1, o, l0, q;
    const float *atQ, *atCtx;
    h16 *atWcH, *atWcL;
    float* atP;
};

__global__ __launch_bounds__(512, 1) void step_k(StepP p) {
    extern __shared__ __align__(16) char sm[];
    const int bid = blockIdx.x;
    const int r0 = p.nAt, r1 = r0 + p.nOut, r2 = r1 + p.nL1, r3 = r2 + p.nL0;

    if (bid >= r0 && bid < r1) {
        mgemm<false, true, 1>(p.o, sm, 0, bid - r0);
    } else if (bid >= r1 && bid < r2) {
        mgemm<true, true, 0>(p.l1, sm, 0, bid - r1);
    } else if (bid >= r2 && bid < r3) {
        mgemm<true, false, 0>(p.l0, sm, 0, bid - r2);
    } else if (bid >= r3) {
        mgemm<false, false, 1>(p.q, sm, 0, bid - r3);
    } else {                              // ATTN: one block per batch b
        int b = bid;
        float* qs = (float*)sm;           // 1024 floats
        float* sc = qs + 1024;            // 64 floats
        const int tx = threadIdx.x;
        *(float2*)&qs[tx * 2] = *(const float2*)&p.atQ[(size_t)b * HH + tx * 2];
        __syncthreads();
        const int wid = tx >> 5, lane = tx & 31;
        for (int s = wid; s < SS; s += 16) {
            const float* cp = p.atCtx + ((size_t)s * BB + b) * HH;
            float acc = 0.f;
#pragma unroll
            for (int i = 0; i < 8; ++i) {
                float4 c4 = *(const float4*)(cp + i * 128 + lane * 4);
                float4 q4 = *(const float4*)&qs[i * 128 + lane * 4];
                acc += c4.x * q4.x + c4.y * q4.y + c4.z * q4.z + c4.w * q4.w;
            }
#pragma unroll
            for (int o = 16; o; o >>= 1) acc += __shfl_down_sync(0xFFFFFFFFu, acc, o);
            if (lane == 0) sc[s] = acc;
        }
        __syncthreads();
        if (tx == 0) {
            float mx = sc[0];
            for (int s = 1; s < SS; ++s) mx = fmaxf(mx, sc[s]);
            float sum = 0.f;
            for (int s = 0; s < SS; ++s) { float e = expf(sc[s] - mx); sc[s] = e; sum += e; }
            float inv = 1.f / sum;
            for (int s = 0; s < SS; ++s) sc[s] *= inv;
        }
        __syncthreads();
        if (tx < SS) p.atP[b * SS + tx] = sc[tx];
        for (int k = tx; k < HH; k += 512) {
            float acc = 0.f;
#pragma unroll 8
            for (int s = 0; s < SS; ++s)
                acc += sc[s] * p.atCtx[((size_t)s * BB + b) * HH + k];
            split2(acc, p.atWcH[(size_t)b * HH + k], p.atWcL[(size_t)b * HH + k]);
        }
    }
}

// ---------------- X0 precompute: emb[input] @ w_ih0^T + biases ----------
__global__ __launch_bounds__(512, 1) void x0_k(StepP p) {
    extern __shared__ __align__(16) char sm[];
    mgemm<false, false, 1>(p.l0, sm, blockIdx.y, blockIdx.x);
}

// ----------------------------- init kernels ----------------------------
__global__ void split_w(const float* __restrict__ w_ih, const float* __restrict__ w_hh,
                        const float* __restrict__ w_in, const float* __restrict__ w_out) {
    const size_t N = 19922944;
    for (size_t i = (size_t)blockIdx.x * 256 + threadIdx.x; i < N;
         i += (size_t)gridDim.x * 256) {
        if (i < 8388608) {
            g_Wih[i] = __float2half_rn(w_ih[i]);
        } else if (i < 16777216) {
            size_t j = i - 8388608; g_Whh[j] = __float2half_rn(w_hh[j]);
        } else if (i < 17825792) {
            size_t j = i - 16777216; g_Win[j] = __float2half_rn(w_in[j]);
        } else {
            size_t j = i - 17825792; g_Wo[j] = __float2half_rn(w_out[j]);
        }
    }
}

__global__ void gather_xe(const int* __restrict__ inp, const float* __restrict__ emb) {
    size_t i = (size_t)blockIdx.x * 256 + threadIdx.x;
    if (i < 4194304) {
        size_t tb = i >> 10, k = i & 1023;
        float v = emb[(size_t)inp[tb] * 1024 + k];
        split2(v, g_XEh[i], g_XEl[i]);
    }
}

__global__ void init_sk(const float* __restrict__ h0, const float* __restrict__ c0) {
    int i = blockIdx.x * 256 + threadIdx.x;
    if (i < BH) {
        float a = h0[i], b = h0[BH + i];
        g_h0F[1][i] = a; split2(a, g_h0H[1][i], g_h0L[1][i]);   // h0(-1): slot 1
        g_h1F[3][i] = b; split2(b, g_h1H[3][i], g_h1L[3][i]);   // h1(-1): slot 3
        g_c0F[i] = c0[i];
        g_c1F[i] = c0[BH + i];
    }
}

__global__ void final_k(float* __restrict__ hf, float* __restrict__ cf,
                        float* __restrict__ at) {
    int i = blockIdx.x * 256 + threadIdx.x;
    if (i < BH) {
        hf[i] = g_h0F[1][i];            // h0(63): 63&1 = 1
        hf[BH + i] = g_h1F[3][i];       // h1(63): 63&3 = 3
        cf[i] = g_c0F[i];
        cf[BH + i] = g_c1F[i];
    }
    if (i < BB * SS) at[i] = g_attn[i];
}

// ------------------------------- launch --------------------------------
extern "C" void kernel_launch(void* const* d_in, const int* in_sizes, int n_in,
                              void* d_out, int out_size) {
    (void)in_sizes; (void)n_in; (void)out_size;
    const int*   inp   = (const int*)d_in[0];
    const float* h0    = (const float*)d_in[1];
    const float* c0    = (const float*)d_in[2];
    const float* ctx   = (const float*)d_in[3];
    const float* emb   = (const float*)d_in[4];
    const float* w_ih  = (const float*)d_in[5];
    const float* w_hh  = (const float*)d_in[6];
    const float* b_ih  = (const float*)d_in[7];
    const float* b_hh  = (const float*)d_in[8];
    const float* w_in  = (const float*)d_in[9];
    const float* w_out = (const float*)d_in[10];

    float* out  = (float*)d_out;
    float* outs = out;
    float* hf   = out + (size_t)TT * BH;
    float* cf   = hf + 2 * BH;
    float* at   = cf + 2 * BH;

    cudaFuncSetAttribute(step_k, cudaFuncAttributeMaxDynamicSharedMemorySize, SMB);
    cudaFuncSetAttribute(x0_k,   cudaFuncAttributeMaxDynamicSharedMemorySize, SMB);

    h16 *Wih, *Whh, *Win, *Wo, *XEh, *XEl;
    h16 *h0H, *h0L, *h1H, *h1L, *wcH, *wcL;
    float *h0F, *h1F, *c0F, *c1F, *qF, *X0, *AT;
    cudaGetSymbolAddress((void**)&Wih, g_Wih); cudaGetSymbolAddress((void**)&Whh, g_Whh);
    cudaGetSymbolAddress((void**)&Win, g_Win); cudaGetSymbolAddress((void**)&Wo,  g_Wo);
    cudaGetSymbolAddress((void**)&XEh, g_XEh); cudaGetSymbolAddress((void**)&XEl, g_XEl);
    cudaGetSymbolAddress((void**)&h0F, g_h0F); cudaGetSymbolAddress((void**)&h1F, g_h1F);
    cudaGetSymbolAddress((void**)&h0H, g_h0H); cudaGetSymbolAddress((void**)&h0L, g_h0L);
    cudaGetSymbolAddress((void**)&h1H, g_h1H); cudaGetSymbolAddress((void**)&h1L, g_h1L);
    cudaGetSymbolAddress((void**)&c0F, g_c0F); cudaGetSymbolAddress((void**)&c1F, g_c1F);
    cudaGetSymbolAddress((void**)&qF,  g_qF);
    cudaGetSymbolAddress((void**)&wcH, g_wcH); cudaGetSymbolAddress((void**)&wcL, g_wcL);
    cudaGetSymbolAddress((void**)&X0,  g_X0);
    cudaGetSymbolAddress((void**)&AT,  g_attn);

    split_w<<<16384, 256>>>(w_ih, w_hh, w_in, w_out);
    gather_xe<<<16384, 256>>>(inp, emb);
    init_sk<<<256, 256>>>(h0, c0);

    {   // X0 = XE @ w_ih0^T + b_ih0 + b_hh0, grid (64 nblk, 64 mblk)
        StepP p = {};
        Seg& s = p.l0;
        s.A1h = XEh; s.A1l = XEl;
        s.W1 = Wih; s.wld = 1024; s.K = 1024;
        s.bias1 = b_ih; s.bias2 = b_hh;
        s.outC = X0; s.ldC = 4096; s.doTanh = 0;
        x0_k<<<dim3(64, 64), 512, SMB>>>(p);
    }

    // Pipeline: launch k carries L1(k-1), OUT(k-4), L0(k), Q(k-2), ATTN(k-3).
    for (int k = 0; k <= 67; ++k) {
        StepP p = {};
        int tL1 = k - 1, tL0 = k, tQ = k - 2, tAt = k - 3, tOut = k - 4;
        if (tL1 >= 0 && tL1 < TT) {
            p.nL1 = 64;
            Seg& s = p.l1;
            s.A1h = h0H + (size_t)(tL1 & 1) * BH; s.A1l = h0L + (size_t)(tL1 & 1) * BH;
            s.A2h = h1H + (size_t)((tL1 - 1) & 3) * BH;
            s.A2l = h1L + (size_t)((tL1 - 1) & 3) * BH;
            s.W1 = Wih + 4194304;
            s.W2 = Whh + 4194304;
            s.wld = 1024; s.K = 2048;
            s.bias1 = b_ih + 4096; s.bias2 = b_hh + 4096;
            s.cSt = c1F;
            s.hF = h1F + (size_t)(tL1 & 3) * BH;
            s.hH = h1H + (size_t)(tL1 & 3) * BH;
            s.hL = h1L + (size_t)(tL1 & 3) * BH;
        }
        if (tOut >= 0 && tOut < TT) {
            p.nOut = 16;
            Seg& s = p.o;
            s.A1h = wcH + (size_t)(tOut & 1) * BH; s.A1l = wcL + (size_t)(tOut & 1) * BH;
            s.A2h = h1H + (size_t)(tOut & 3) * BH; s.A2l = h1L + (size_t)(tOut & 3) * BH;
            s.W1 = Wo;
            s.W2 = Wo + 1024;
            s.wld = 2048; s.K = 2048;
            s.outC = outs + (size_t)tOut * BH; s.ldC = HH; s.doTanh = 1;
        }
        if (tL0 >= 0 && tL0 < TT) {
            p.nL0 = 64;
            Seg& s = p.l0;
            s.A1h = h0H + (size_t)((tL0 + 1) & 1) * BH;
            s.A1l = h0L + (size_t)((tL0 + 1) & 1) * BH;
            s.W1 = Whh; s.wld = 1024; s.K = 1024;
            s.addC = X0 + (size_t)tL0 * 64 * 4096;
            s.cSt = c0F;
            s.hF = h0F + (size_t)(tL0 & 1) * BH;
            s.hH = h0H + (size_t)(tL0 & 1) * BH;
            s.hL = h0L + (size_t)(tL0 & 1) * BH;
        }
        if (tQ >= 0 && tQ < TT) {
            p.nQ = 16;
            Seg& s = p.q;
            s.A1h = h1H + (size_t)(tQ & 3) * BH; s.A1l = h1L + (size_t)(tQ & 3) * BH;
            s.W1 = Win; s.wld = 1024; s.K = 1024;
            s.outC = qF + (size_t)(tQ & 1) * BH; s.ldC = HH; s.doTanh = 0;
        }
        if (tAt >= 0 && tAt < TT) {
            p.nAt = 64;
            p.atQ = qF + (size_t)(tAt & 1) * BH;
            p.atCtx = ctx;
            p.atWcH = wcH + (size_t)(tAt & 1) * BH;
            p.atWcL = wcL + (size_t)(tAt & 1) * BH;
            p.atP = AT;
        }
        int grid = p.nL1 + p.nOut + p.nL0 + p.nQ + p.nAt;
        if (grid > 0) step_k<<<grid, 512, SMB>>>(p);
    }

    final_k<<<512, 256>>>(hf, cf, at);
}

// round 11
// speedup vs baseline: 2.0020x; 1.2179x over previous
#include <cuda_runtime.h>
#include <cuda_fp16.h>
#include <cstdint>

// Decoder: 2-layer LSTM + Luong attention. T=B=S=64, H=E=1024, L=2.
// mma.sync fp16 (A single fp16, W single fp16; X0 precompute uses hi/lo A),
// 64x64 tiles, 512 threads = 4 warpgroups, 4-way K-split, k16 chunks,
// 4-stage cp.async pipeline, traffic-balanced block order.

#define TT 64
#define BB 64
#define SS 64
#define HH 1024
#define BH (BB * HH)

typedef unsigned long long ull;
typedef __half h16;

__device__ __forceinline__ float sigm_(float x) { return 1.f / (1.f + expf(-x)); }
__device__ __forceinline__ void split2(float v, h16& hi, h16& lo) {
    hi = __float2half_rn(v);
    lo = __float2half_rn(v - __half2float(hi));
}

// ------------------------------- scratch -------------------------------
__device__ __align__(256) h16 g_Wih[8388608];      // [2][4096][1024]
__device__ __align__(256) h16 g_Whh[8388608];
__device__ __align__(256) h16 g_Win[1048576];
__device__ __align__(256) h16 g_Wo[2097152];       // [1024][2048]
__device__ __align__(256) h16 g_XEh[4194304], g_XEl[4194304];
__device__ float g_X0[(size_t)4096 * 4096];        // [t*64+b][4096 gate cols]
__device__ float g_h0F[2][BH], g_h1F[4][BH], g_c0F[BH], g_c1F[BH];
__device__ __align__(256) h16 g_h0H[2][BH];
__device__ __align__(256) h16 g_h1H[4][BH];
__device__ __align__(256) h16 g_wcH[2][BH];
__device__ float g_qF[2][BH];
__device__ float g_attn[BB * SS];

// ----------------------------- ptx helpers -----------------------------
__device__ __forceinline__ uint32_t s2u(const void* p) {
    uint32_t a;
    asm("{ .reg .u64 t; cvta.to.shared.u64 t, %1; cvt.u32.u64 %0, t; }"
        : "=r"(a) : "l"(p));
    return a;
}
__device__ __forceinline__ void cpa16(uint32_t dst, const void* src) {
    asm volatile("cp.async.cg.shared.global [%0], [%1], 16;"
                 :: "r"(dst), "l"(src) : "memory");
}
__device__ __forceinline__ void ldsm4(uint32_t* r, uint32_t addr) {
    asm volatile("ldmatrix.sync.aligned.m8n8.x4.shared.b16 {%0,%1,%2,%3}, [%4];"
                 : "=r"(r[0]), "=r"(r[1]), "=r"(r[2]), "=r"(r[3]) : "r"(addr));
}
__device__ __forceinline__ void mma16816(float* d, const uint32_t* a, const uint32_t* b) {
    asm volatile(
        "mma.sync.aligned.m16n8k16.row.col.f32.f16.f16.f32 "
        "{%0,%1,%2,%3},{%4,%5,%6,%7},{%8,%9},{%0,%1,%2,%3};"
        : "+f"(d[0]), "+f"(d[1]), "+f"(d[2]), "+f"(d[3])
        : "r"(a[0]), "r"(a[1]), "r"(a[2]), "r"(a[3]), "r"(b[0]), "r"(b[1]));
}
__device__ __forceinline__ void barw(int wg) {
    asm volatile("bar.sync %0, 128;" :: "r"(wg + 1) : "memory");
}

// ---------------------------- GEMM segment -----------------------------
// C[64 m(batch), 64 n] = A @ W^T. 512 threads = 4 wgs of 128; each wg does
// a K-slice into a partial accumulator; combined in epilogue.
// A single fp16; W single fp16. DUALA: A has hi/lo pair (A1=hi, A2=lo)
// sharing one W load (used by the X0 precompute for full A precision).
// GATE: n cols = 4 gates x 16 hidden units. PAIR2: K=2048 (wg pair = half).
struct Seg {
    const h16 *A1, *A2;
    const h16 *W1, *W2;
    int wld, K;
    const float *addC, *bias1, *bias2;
    float *cSt, *hF;
    h16 *hH;
    float *outC; int ldC, doTanh;
};

// per-wg stage (k16), rows 64 x 48B (32B data + 16B pad, conflict-free):
//   normal: A 3072 | W 3072               = 6144 B
//   DUALA : Ah 3072 | Al 3072 | W 3072    = 9216 B
// 4 stages/wg x 4 wg: step 98304 B, x0 147456 B dynamic smem.
#define SMB_STEP (4 * 4 * 6144)
#define SMB_X0   (4 * 4 * 9216)

template <bool GATE, bool PAIR2, bool DUALA, int EPI>
__device__ void mgemm(const Seg& a, char* sm, int mblk, int nblk) {
    const int STG  = DUALA ? 9216 : 6144;
    const int WOFF = DUALA ? 6144 : 3072;
    const int tx = threadIdx.x;
    const int wg = tx >> 7;              // warpgroup 0..3
    const int wtx = tx & 127;
    const int warp = wtx >> 5, lane = tx & 31;
    const int wm = warp << 4;            // warp m offset; n covers all 64
    const uint32_t smb = s2u(sm) + wg * (4 * STG);

    // staging: thread -> (row 0..63, 16B unit 0..1)
    const int sr = wtx >> 1, su = wtx & 1;
    const int am = mblk * 64 + sr;
    const int wr = GATE ? ((sr >> 4) * HH + nblk * 16 + (sr & 15))
                        : (nblk * 64 + sr);

    // per-wg operands and K range
    const h16 *a1, *a2, *w1;
    int kbase, Kwg;
    if (PAIR2) {
        int p = wg >> 1;
        a1 = p ? a.A2 : a.A1;
        w1 = p ? a.W2 : a.W1;
        a2 = nullptr;
        kbase = (wg & 1) << 9; Kwg = 512;
    } else {
        a1 = a.A1; a2 = a.A2; w1 = a.W1;
        Kwg = a.K >> 2; kbase = wg * Kwg;
    }
    const size_t arow = (size_t)am * 1024;
    const size_t wrow = (size_t)wr * a.wld;

    float acc[8][4] = {};
    const int nc = Kwg >> 4;             // k16 chunks

    const uint32_t aoff = (uint32_t)((wm + (lane & 15)) * 48 + ((lane >> 4) << 4));
    const uint32_t boff = (uint32_t)(((((lane >> 4) << 3) + (lane & 7))) * 48
                                     + (((lane >> 3) & 1) << 4));

#define STAGE(c)                                                               \
    {                                                                          \
        int kl = kbase + ((c) << 4);                                           \
        uint32_t db = smb + ((c) & 3) * STG + sr * 48 + (su << 4);             \
        cpa16(db, a1 + arow + kl + su * 8);                                    \
        if (DUALA) cpa16(db + 3072, a2 + arow + kl + su * 8);                  \
        cpa16(db + WOFF, w1 + wrow + kl + su * 8);                             \
        asm volatile("cp.async.commit_group;" ::: "memory");                   \
    }

    STAGE(0) STAGE(1) STAGE(2)
    for (int c = 0; c < nc; ++c) {
        if (c + 3 < nc) {
            asm volatile("cp.async.wait_group 2;" ::: "memory");
            barw(wg);
            STAGE(c + 3)
        } else {
            asm volatile("cp.async.wait_group 0;" ::: "memory");
            barw(wg);
        }
        const uint32_t base = smb + (c & 3) * STG;
        uint32_t ah[4], al[4], bw[16];
        ldsm4(ah, base + aoff);
        if (DUALA) ldsm4(al, base + 3072 + aoff);
#pragma unroll
        for (int j = 0; j < 4; ++j)
            ldsm4(bw + 4 * j, base + WOFF + boff + j * 16 * 48);
#pragma unroll
        for (int nt = 0; nt < 8; ++nt) {
            mma16816(acc[nt], ah, bw + 2 * nt);
            if (DUALA) mma16816(acc[nt], al, bw + 2 * nt);
        }
    }
#undef STAGE
    __syncthreads();   // all wgs done with buffers before St staging

    // stage partial C: wg i -> St[i*4224 ..]
    float* St = (float*)sm;
    float* Sw = St + wg * 4224;          // 64*66
    const int rr = wm + (lane >> 2);
#pragma unroll
    for (int nt = 0; nt < 8; ++nt) {
        int cc = nt * 8 + ((lane & 3) << 1);
        Sw[cc * 66 + rr]           = acc[nt][0];
        Sw[(cc + 1) * 66 + rr]     = acc[nt][1];
        Sw[cc * 66 + rr + 8]       = acc[nt][2];
        Sw[(cc + 1) * 66 + rr + 8] = acc[nt][3];
    }
    __syncthreads();

    if (EPI == 0) {      // fused LSTM cell: cols = gate*16 + jj
#pragma unroll
        for (int it = 0; it < 2; ++it) {
            int idx = tx + it * 512;
            int b = idx & 63, jj = idx >> 6;          // jj 0..15
            int jg = nblk * 16 + jj;
            float gi = St[jj * 66 + b]        + St[4224 + jj * 66 + b]
                     + St[8448 + jj * 66 + b] + St[12672 + jj * 66 + b];
            float gf = St[(16 + jj) * 66 + b]        + St[4224 + (16 + jj) * 66 + b]
                     + St[8448 + (16 + jj) * 66 + b] + St[12672 + (16 + jj) * 66 + b];
            float gg = St[(32 + jj) * 66 + b]        + St[4224 + (32 + jj) * 66 + b]
                     + St[8448 + (32 + jj) * 66 + b] + St[12672 + (32 + jj) * 66 + b];
            float go = St[(48 + jj) * 66 + b]        + St[4224 + (48 + jj) * 66 + b]
                     + St[8448 + (48 + jj) * 66 + b] + St[12672 + (48 + jj) * 66 + b];
            if (a.addC) {
                const float* ac = a.addC + (size_t)b * 4096 + jg;
                gi += ac[0]; gf += ac[1024]; gg += ac[2048]; go += ac[3072];
            }
            if (a.bias1) {
                gi += a.bias1[jg] + a.bias2[jg];
                gf += a.bias1[1024 + jg] + a.bias2[1024 + jg];
                gg += a.bias1[2048 + jg] + a.bias2[2048 + jg];
                go += a.bias1[3072 + jg] + a.bias2[3072 + jg];
            }
            float cc2 = sigm_(gf) * a.cSt[b * HH + jg] + sigm_(gi) * tanhf(gg);
            a.cSt[b * HH + jg] = cc2;
            float h = sigm_(go) * tanhf(cc2);
            a.hF[b * HH + jg] = h;
            a.hH[b * HH + jg] = __float2half_rn(h);
        }
    } else {             // plain store (optional bias / tanh)
#pragma unroll
        for (int it = 0; it < 8; ++it) {
            int idx = tx + it * 512;
            int row = idx >> 6, col = idx & 63;
            float v = St[col * 66 + row]        + St[4224 + col * 66 + row]
                    + St[8448 + col * 66 + row] + St[12672 + col * 66 + row];
            int cg = nblk * 64 + col;
            if (a.bias1) v += a.bias1[cg] + a.bias2[cg];
            if (a.doTanh) v = tanhf(v);
            a.outC[(size_t)(mblk * 64 + row) * a.ldC + cg] = v;
        }
    }
}

// ------------------------------ step kernel ----------------------------
// Block order (L2-traffic balance with bid/bid+148 SM pairing):
//   [ATTN, OUT, L1, L0, Q] -- heavy L1 sits in single-block bid range.
struct StepP {
    int nL1, nOut, nL0, nQ, nAt;
    Seg l1, o, l0, q;
    const float *atQ, *atCtx;
    h16 *atWc;
    float* atP;
};

__global__ __launch_bounds__(512, 1) void step_k(StepP p) {
    extern __shared__ __align__(16) char sm[];
    const int bid = blockIdx.x;
    const int r0 = p.nAt, r1 = r0 + p.nOut, r2 = r1 + p.nL1, r3 = r2 + p.nL0;

    if (bid >= r0 && bid < r1) {
        mgemm<false, true, false, 1>(p.o, sm, 0, bid - r0);
    } else if (bid >= r1 && bid < r2) {
        mgemm<true, true, false, 0>(p.l1, sm, 0, bid - r1);
    } else if (bid >= r2 && bid < r3) {
        mgemm<true, false, false, 0>(p.l0, sm, 0, bid - r2);
    } else if (bid >= r3) {
        mgemm<false, false, false, 1>(p.q, sm, 0, bid - r3);
    } else {                              // ATTN: one block per batch b
        int b = bid;
        float* qs = (float*)sm;           // 1024 floats
        float* sc = qs + 1024;            // 64 floats
        const int tx = threadIdx.x;
        *(float2*)&qs[tx * 2] = *(const float2*)&p.atQ[(size_t)b * HH + tx * 2];
        __syncthreads();
        const int wid = tx >> 5, lane = tx & 31;
        for (int s = wid; s < SS; s += 16) {
            const float* cp = p.atCtx + ((size_t)s * BB + b) * HH;
            float acc = 0.f;
#pragma unroll
            for (int i = 0; i < 8; ++i) {
                float4 c4 = *(const float4*)(cp + i * 128 + lane * 4);
                float4 q4 = *(const float4*)&qs[i * 128 + lane * 4];
                acc += c4.x * q4.x + c4.y * q4.y + c4.z * q4.z + c4.w * q4.w;
            }
#pragma unroll
            for (int o = 16; o; o >>= 1) acc += __shfl_down_sync(0xFFFFFFFFu, acc, o);
            if (lane == 0) sc[s] = acc;
        }
        __syncthreads();
        if (tx == 0) {
            float mx = sc[0];
            for (int s = 1; s < SS; ++s) mx = fmaxf(mx, sc[s]);
            float sum = 0.f;
            for (int s = 0; s < SS; ++s) { float e = expf(sc[s] - mx); sc[s] = e; sum += e; }
            float inv = 1.f / sum;
            for (int s = 0; s < SS; ++s) sc[s] *= inv;
        }
        __syncthreads();
        if (tx < SS) p.atP[b * SS + tx] = sc[tx];
        for (int k = tx; k < HH; k += 512) {
            float acc = 0.f;
#pragma unroll 8
            for (int s = 0; s < SS; ++s)
                acc += sc[s] * p.atCtx[((size_t)s * BB + b) * HH + k];
            p.atWc[(size_t)b * HH + k] = __float2half_rn(acc);
        }
    }
}

// ---------------- X0 precompute: emb[input] @ w_ih0^T + biases ----------
// DUALA: A = XE hi/lo pair for full input precision (off critical path).
__global__ __launch_bounds__(512, 1) void x0_k(StepP p) {
    extern __shared__ __align__(16) char sm[];
    mgemm<false, false, true, 1>(p.l0, sm, blockIdx.y, blockIdx.x);
}

// ----------------------------- init kernels ----------------------------
__global__ void split_w(const float* __restrict__ w_ih, const float* __restrict__ w_hh,
                        const float* __restrict__ w_in, const float* __restrict__ w_out) {
    const size_t N = 19922944;
    for (size_t i = (size_t)blockIdx.x * 256 + threadIdx.x; i < N;
         i += (size_t)gridDim.x * 256) {
        if (i < 8388608) {
            g_Wih[i] = __float2half_rn(w_ih[i]);
        } else if (i < 16777216) {
            size_t j = i - 8388608; g_Whh[j] = __float2half_rn(w_hh[j]);
        } else if (i < 17825792) {
            size_t j = i - 16777216; g_Win[j] = __float2half_rn(w_in[j]);
        } else {
            size_t j = i - 17825792; g_Wo[j] = __float2half_rn(w_out[j]);
        }
    }
}

__global__ void gather_xe(const int* __restrict__ inp, const float* __restrict__ emb) {
    size_t i = (size_t)blockIdx.x * 256 + threadIdx.x;
    if (i < 4194304) {
        size_t tb = i >> 10, k = i & 1023;
        float v = emb[(size_t)inp[tb] * 1024 + k];
        split2(v, g_XEh[i], g_XEl[i]);
    }
}

__global__ void init_sk(const float* __restrict__ h0, const float* __restrict__ c0) {
    int i = blockIdx.x * 256 + threadIdx.x;
    if (i < BH) {
        float a = h0[i], b = h0[BH + i];
        g_h0F[1][i] = a; g_h0H[1][i] = __float2half_rn(a);   // h0(-1): slot 1
        g_h1F[3][i] = b; g_h1H[3][i] = __float2half_rn(b);   // h1(-1): slot 3
        g_c0F[i] = c0[i];
        g_c1F[i] = c0[BH + i];
    }
}

__global__ void final_k(float* __restrict__ hf, float* __restrict__ cf,
                        float* __restrict__ at) {
    int i = blockIdx.x * 256 + threadIdx.x;
    if (i < BH) {
        hf[i] = g_h0F[1][i];            // h0(63): 63&1 = 1
        hf[BH + i] = g_h1F[3][i];       // h1(63): 63&3 = 3
        cf[i] = g_c0F[i];
        cf[BH + i] = g_c1F[i];
    }
    if (i < BB * SS) at[i] = g_attn[i];
}

// ------------------------------- launch --------------------------------
extern "C" void kernel_launch(void* const* d_in, const int* in_sizes, int n_in,
                              void* d_out, int out_size) {
    (void)in_sizes; (void)n_in; (void)out_size;
    const int*   inp   = (const int*)d_in[0];
    const float* h0    = (const float*)d_in[1];
    const float* c0    = (const float*)d_in[2];
    const float* ctx   = (const float*)d_in[3];
    const float* emb   = (const float*)d_in[4];
    const float* w_ih  = (const float*)d_in[5];
    const float* w_hh  = (const float*)d_in[6];
    const float* b_ih  = (const float*)d_in[7];
    const float* b_hh  = (const float*)d_in[8];
    const float* w_in  = (const float*)d_in[9];
    const float* w_out = (const float*)d_in[10];

    float* out  = (float*)d_out;
    float* outs = out;
    float* hf   = out + (size_t)TT * BH;
    float* cf   = hf + 2 * BH;
    float* at   = cf + 2 * BH;

    cudaFuncSetAttribute(step_k, cudaFuncAttributeMaxDynamicSharedMemorySize, SMB_STEP);
    cudaFuncSetAttribute(x0_k,   cudaFuncAttributeMaxDynamicSharedMemorySize, SMB_X0);

    h16 *Wih, *Whh, *Win, *Wo, *XEh, *XEl;
    h16 *h0H, *h1H, *wcH;
    float *h0F, *h1F, *c0F, *c1F, *qF, *X0, *AT;
    cudaGetSymbolAddress((void**)&Wih, g_Wih); cudaGetSymbolAddress((void**)&Whh, g_Whh);
    cudaGetSymbolAddress((void**)&Win, g_Win); cudaGetSymbolAddress((void**)&Wo,  g_Wo);
    cudaGetSymbolAddress((void**)&XEh, g_XEh); cudaGetSymbolAddress((void**)&XEl, g_XEl);
    cudaGetSymbolAddress((void**)&h0F, g_h0F); cudaGetSymbolAddress((void**)&h1F, g_h1F);
    cudaGetSymbolAddress((void**)&h0H, g_h0H); cudaGetSymbolAddress((void**)&h1H, g_h1H);
    cudaGetSymbolAddress((void**)&c0F, g_c0F); cudaGetSymbolAddress((void**)&c1F, g_c1F);
    cudaGetSymbolAddress((void**)&qF,  g_qF);
    cudaGetSymbolAddress((void**)&wcH, g_wcH);
    cudaGetSymbolAddress((void**)&X0,  g_X0);
    cudaGetSymbolAddress((void**)&AT,  g_attn);

    split_w<<<16384, 256>>>(w_ih, w_hh, w_in, w_out);
    gather_xe<<<16384, 256>>>(inp, emb);
    init_sk<<<256, 256>>>(h0, c0);

    {   // X0 = XEh@W + XEl@W + biases, grid (64 nblk, 64 mblk), DUALA path
        StepP p = {};
        Seg& s = p.l0;
        s.A1 = XEh; s.A2 = XEl;
        s.W1 = Wih; s.wld = 1024; s.K = 1024;
        s.bias1 = b_ih; s.bias2 = b_hh;
        s.outC = X0; s.ldC = 4096; s.doTanh = 0;
        x0_k<<<dim3(64, 64), 512, SMB_X0>>>(p);
    }

    // Pipeline: launch k carries L1(k-1), OUT(k-4), L0(k), Q(k-2), ATTN(k-3).
    for (int k = 0; k <= 67; ++k) {
        StepP p = {};
        int tL1 = k - 1, tL0 = k, tQ = k - 2, tAt = k - 3, tOut = k - 4;
        if (tL1 >= 0 && tL1 < TT) {
            p.nL1 = 64;
            Seg& s = p.l1;
            s.A1 = h0H + (size_t)(tL1 & 1) * BH;
            s.A2 = h1H + (size_t)((tL1 - 1) & 3) * BH;
            s.W1 = Wih + 4194304;
            s.W2 = Whh + 4194304;
            s.wld = 1024; s.K = 2048;
            s.bias1 = b_ih + 4096; s.bias2 = b_hh + 4096;
            s.cSt = c1F;
            s.hF = h1F + (size_t)(tL1 & 3) * BH;
            s.hH = h1H + (size_t)(tL1 & 3) * BH;
        }
        if (tOut >= 0 && tOut < TT) {
            p.nOut = 16;
            Seg& s = p.o;
            s.A1 = wcH + (size_t)(tOut & 1) * BH;
            s.A2 = h1H + (size_t)(tOut & 3) * BH;
            s.W1 = Wo;
            s.W2 = Wo + 1024;
            s.wld = 2048; s.K = 2048;
            s.outC = outs + (size_t)tOut * BH; s.ldC = HH; s.doTanh = 1;
        }
        if (tL0 >= 0 && tL0 < TT) {
            p.nL0 = 64;
            Seg& s = p.l0;
            s.A1 = h0H + (size_t)((tL0 + 1) & 1) * BH;
            s.W1 = Whh; s.wld = 1024; s.K = 1024;
            s.addC = X0 + (size_t)tL0 * 64 * 4096;
            s.cSt = c0F;
            s.hF = h0F + (size_t)(tL0 & 1) * BH;
            s.hH = h0H + (size_t)(tL0 & 1) * BH;
        }
        if (tQ >= 0 && tQ < TT) {
            p.nQ = 16;
            Seg& s = p.q;
            s.A1 = h1H + (size_t)(tQ & 3) * BH;
            s.W1 = Win; s.wld = 1024; s.K = 1024;
            s.outC = qF + (size_t)(tQ & 1) * BH; s.ldC = HH; s.doTanh = 0;
        }
        if (tAt >= 0 && tAt < TT) {
            p.nAt = 64;
            p.atQ = qF + (size_t)(tAt & 1) * BH;
            p.atCtx = ctx;
            p.atWc = wcH + (size_t)(tAt & 1) * BH;
            p.atP = AT;
        }
        int grid = p.nL1 + p.nOut + p.nL0 + p.nQ + p.nAt;
        if (grid > 0) step_k<<<grid, 512, SMB_STEP>>>(p);
    }

    final_k<<<512, 256>>>(hf, cf, at);
}